// round 7
// baseline (speedup 1.0000x reference)
#include <cuda_runtime.h>

#define NN 100000
#define EE 3200000
#define FIN 128
#define CAP 128                // fixed bucket capacity per node
#define GEMM1_BLKS 782         // ceil(NN/128)
#define HIST_BLKS 25000        // ceil(EE/128)
#define RT1 5                  // cached groups layer1 (deg <= 40)
#define RT2 3                  // cached groups layer2 (deg <= 48)
#define L2E 1.44269504f

// ---------------- scratch (static device globals; no allocs) ----------------
__device__ int   g_cnt[NN];          // zero at load; re-zeroed by k_edge2h
__device__ int   g_srcs[NN * CAP];   // fixed-capacity CSR buckets
__device__ int   g_ovf_cnt;          // overflow count (build writes)
__device__ int   g_ovf_cnt2;         // snapshot (edge1 writes, edge2h reads)
__device__ int   g_ovfd[EE];         // overflow dst (cold)
__device__ int   g_ovfs[EE];         // overflow src (cold)
__device__ float g_p[NN * CAP];      // uncached-group attention weights
__device__ float g_xl1[NN * 16];
__device__ float g_xr1[NN * 16];
__device__ float g_lin1[NN * 16];
__device__ float g_xl2[NN * 8];
__device__ float g_xr2[NN * 8];
__device__ float g_lin2[NN * 8];

__device__ __forceinline__ float ex2f(float x) {
    float y; asm("ex2.approx.f32 %0, %1;" : "=f"(y) : "f"(x)); return y;
}

// ---- fused build: layer-1 GEMM (blocks 0..781) + bucket scatter (rest) -----
__global__ void __launch_bounds__(128) k_build(
    const int* __restrict__ src, const int* __restrict__ dst,
    const float* __restrict__ x, const float* __restrict__ Wl,
    const float* __restrict__ Wr, const float* __restrict__ Wlin,
    const float* __restrict__ blin)
{
    __shared__ float sx[128][36];
    __shared__ float sw[32][48];
    int t = threadIdx.x;
    int b = blockIdx.x;

    if (b >= GEMM1_BLKS) {
        int e = (b - GEMM1_BLKS) * 128 + t;
        if (e < EE) {
            int d = dst[e];
            int r = atomicAdd(&g_cnt[d], 1);
            if (r < CAP) {
                g_srcs[d * CAP + r] = src[e];
            } else {
                int o = atomicAdd(&g_ovf_cnt, 1);
                g_ovfd[o] = d;
                g_ovfs[o] = src[e];
            }
        }
        return;
    }

    // ---- gemm1: tile 128 rows x 48 cols; thread: 8 rows (stride 16) x 6 cols
    int cg = t & 7, rg = t >> 3;         // cg 0..7, rg 0..15
    int c0 = cg * 6;
    int rowbase = b * 128;
    float acc[8][6];
#pragma unroll
    for (int i = 0; i < 8; i++)
#pragma unroll
        for (int j = 0; j < 6; j++) acc[i][j] = 0.f;

    for (int kb = 0; kb < FIN; kb += 32) {
#pragma unroll
        for (int n = 0; n < 8; n++) {
            int idx = t + n * 128;
            int r = idx >> 3, k4 = idx & 7;
            int gr = rowbase + r;
            float4 val = make_float4(0.f, 0.f, 0.f, 0.f);
            if (gr < NN) val = *(const float4*)(x + gr * FIN + kb + k4 * 4);
            *(float4*)&sx[r][k4 * 4] = val;
        }
        for (int idx = t; idx < 32 * 48; idx += 128) {
            int k = idx / 48, j = idx % 48;
            int gk = kb + k;
            float val;
            if (j < 16)      val = Wl[gk * 16 + j];
            else if (j < 32) val = Wr[gk * 16 + j - 16];
            else             val = Wlin[gk * 16 + j - 32];
            sw[k][j] = val;
        }
        __syncthreads();
#pragma unroll
        for (int k = 0; k < 32; k += 4) {
            float4 xv4[8];
#pragma unroll
            for (int i = 0; i < 8; i++)
                xv4[i] = *(const float4*)&sx[rg + 16 * i][k];
#pragma unroll
            for (int kk = 0; kk < 4; kk++) {
                float wv[6];
#pragma unroll
                for (int j = 0; j < 6; j++) wv[j] = sw[k + kk][c0 + j];
#pragma unroll
                for (int i = 0; i < 8; i++) {
                    float xs = kk == 0 ? xv4[i].x : kk == 1 ? xv4[i].y
                             : kk == 2 ? xv4[i].z : xv4[i].w;
#pragma unroll
                    for (int j = 0; j < 6; j++)
                        acc[i][j] = fmaf(xs, wv[j], acc[i][j]);
                }
            }
        }
        __syncthreads();
    }
#pragma unroll
    for (int i = 0; i < 8; i++) {
        int gr = rowbase + rg + 16 * i;
        if (gr < NN) {
#pragma unroll
            for (int j = 0; j < 6; j++) {
                int c = c0 + j;
                if (c < 16)      g_xl1[gr * 16 + c] = acc[i][j];
                else if (c < 32) g_xr1[gr * 16 + (c - 16)] = acc[i][j];
                else             g_lin1[gr * 16 + (c - 32)] = acc[i][j] + blin[c - 32];
            }
        }
    }
}

// ------ edge layer 1 (4 lanes/edge) + fused layer-2 node GEMM epilogue ------
__global__ void __launch_bounds__(256) k_edge1(
    const float* __restrict__ att, const float* __restrict__ bias,
    const float* __restrict__ tptr,
    const float* __restrict__ Wl2, const float* __restrict__ Wr2,
    const float* __restrict__ Wlin2, const float* __restrict__ blin2)
{
    __shared__ float s_w2[16 * 24];
    __shared__ float s_b2[8];
    {
        int t = threadIdx.x;
        for (int idx = t; idx < 16 * 24; idx += 256) {
            int k = idx / 24, j = idx % 24;
            float v;
            if (j < 8)       v = Wl2[k * 8 + j];
            else if (j < 16) v = Wr2[k * 8 + j - 8];
            else             v = Wlin2[k * 8 + j - 16];
            s_w2[idx] = v;
        }
        if (t < 8) s_b2[t] = blin2[t];
        if (blockIdx.x == 0 && t == 0) g_ovf_cnt2 = g_ovf_cnt;
    }
    __syncthreads();

    int w = threadIdx.x >> 5;
    int lane = threadIdx.x & 31;
    int node = blockIdx.x * 8 + w;
    if (node >= NN) return;
    int q = lane & 3, e8 = lane >> 2;
    int deg = g_cnt[node];
    int degf = deg < CAP ? deg : CAP;
    const int* sp = g_srcs + node * CAP;
    float tl2e = tptr[0] * L2E;
    float4 a4 = *(const float4*)(att + q * 4);
    float4 xr = *(const float4*)(g_xr1 + node * 16 + q * 4);
    float a06x = 0.6f * L2E * a4.x, a06y = 0.6f * L2E * a4.y;
    float a06z = 0.6f * L2E * a4.z, a06w = 0.6f * L2E * a4.w;
    float a04x = 0.4f * L2E * a4.x, a04y = 0.4f * L2E * a4.y;
    float a04z = 0.4f * L2E * a4.z, a04w = 0.4f * L2E * a4.w;
    int nfull = degf >> 3, rem = degf & 7;
    int itc = nfull < RT1 ? nfull : RT1;

    float4 mreg[RT1];
    float  preg[RT1];

    // ---- pass 1A: cached full groups (no masks) ----
    float S = 0.f;
#pragma unroll
    for (int it = 0; it < RT1; it++) {
        if (it >= itc) break;
        int kk = it * 8 + e8;
        int s = sp[kk];
        float4 m = *(const float4*)(g_xl1 + s * 16 + q * 4);
        float y0 = m.x + xr.x, y1 = m.y + xr.y, y2 = m.z + xr.z, y3 = m.w + xr.w;
        float sc = a06x * y0;
        sc = fmaf(a04x, fabsf(y0), sc);
        sc = fmaf(a06y, y1, sc); sc = fmaf(a04y, fabsf(y1), sc);
        sc = fmaf(a06z, y2, sc); sc = fmaf(a04z, fabsf(y2), sc);
        sc = fmaf(a06w, y3, sc); sc = fmaf(a04w, fabsf(y3), sc);
        sc += __shfl_xor_sync(0xffffffffu, sc, 1);
        sc += __shfl_xor_sync(0xffffffffu, sc, 2);
        float p = ex2f(sc);
        mreg[it] = m; preg[it] = p;
        S += p;
    }
    // ---- pass 1B: uncached full groups (rare) ----
    for (int it = RT1; it < nfull; it++) {
        int kk = it * 8 + e8;
        int s = sp[kk];
        float4 m = *(const float4*)(g_xl1 + s * 16 + q * 4);
        float y0 = m.x + xr.x, y1 = m.y + xr.y, y2 = m.z + xr.z, y3 = m.w + xr.w;
        float sc = a06x * y0;
        sc = fmaf(a04x, fabsf(y0), sc);
        sc = fmaf(a06y, y1, sc); sc = fmaf(a04y, fabsf(y1), sc);
        sc = fmaf(a06z, y2, sc); sc = fmaf(a04z, fabsf(y2), sc);
        sc = fmaf(a06w, y3, sc); sc = fmaf(a04w, fabsf(y3), sc);
        sc += __shfl_xor_sync(0xffffffffu, sc, 1);
        sc += __shfl_xor_sync(0xffffffffu, sc, 2);
        float p = ex2f(sc);
        g_p[node * CAP + kk] = p;
        S += p;
    }
    // ---- pass 1C: remainder group (masked; cached iff nfull < RT1) ----
    if (rem) {
        int kk = nfull * 8 + e8;
        bool v = e8 < rem;
        float4 m = make_float4(0.f, 0.f, 0.f, 0.f);
        if (v) m = *(const float4*)(g_xl1 + sp[kk] * 16 + q * 4);
        float y0 = m.x + xr.x, y1 = m.y + xr.y, y2 = m.z + xr.z, y3 = m.w + xr.w;
        float sc = a06x * y0;
        sc = fmaf(a04x, fabsf(y0), sc);
        sc = fmaf(a06y, y1, sc); sc = fmaf(a04y, fabsf(y1), sc);
        sc = fmaf(a06z, y2, sc); sc = fmaf(a04z, fabsf(y2), sc);
        sc = fmaf(a06w, y3, sc); sc = fmaf(a04w, fabsf(y3), sc);
        sc += __shfl_xor_sync(0xffffffffu, sc, 1);
        sc += __shfl_xor_sync(0xffffffffu, sc, 2);
        float p = v ? ex2f(sc) : 0.f;
        if (nfull < RT1) {
#pragma unroll
            for (int j = 0; j < RT1; j++)
                if (j == nfull) { mreg[j] = m; preg[j] = p; }
        } else {
            g_p[node * CAP + kk] = p;
        }
        S += p;
    }
    // ---- pass 1: overflow list (cold) ----
    if (deg > CAP) {
        int ovfn = g_ovf_cnt;
        for (int i = 0; i < ovfn; i++) {
            if (g_ovfd[i] == node) {
                float4 m = make_float4(0.f, 0.f, 0.f, 0.f);
                if (e8 == 0) m = *(const float4*)(g_xl1 + g_ovfs[i] * 16 + q * 4);
                float y0 = m.x + xr.x, y1 = m.y + xr.y, y2 = m.z + xr.z, y3 = m.w + xr.w;
                float sc = a06x * y0;
                sc = fmaf(a04x, fabsf(y0), sc);
                sc = fmaf(a06y, y1, sc); sc = fmaf(a04y, fabsf(y1), sc);
                sc = fmaf(a06z, y2, sc); sc = fmaf(a04z, fabsf(y2), sc);
                sc = fmaf(a06w, y3, sc); sc = fmaf(a04w, fabsf(y3), sc);
                sc += __shfl_xor_sync(0xffffffffu, sc, 1);
                sc += __shfl_xor_sync(0xffffffffu, sc, 2);
                if (e8 == 0) S += ex2f(sc);
            }
        }
    }
#pragma unroll
    for (int o = 16; o; o >>= 1) S += __shfl_xor_sync(0xffffffffu, S, o);
    float rinv = __fdividef(4.f, S);   // S counted 4x per edge
    __syncwarp();

    // ---- pass 2A: cached (pure register math) ----
    float4 num = make_float4(0.f, 0.f, 0.f, 0.f);
    float4 den = make_float4(0.f, 0.f, 0.f, 0.f);
#pragma unroll
    for (int it = 0; it < RT1; it++) {
        if (it >= itc) break;
        float4 m = mreg[it];
        float a = preg[it] * rinv;
        float we = a * tl2e;
        float e0 = ex2f(m.x * we);
        float e1 = ex2f(m.y * we);
        float e2 = ex2f(m.z * we);
        float e3 = ex2f(m.w * we);
        den.x += e0; den.y += e1; den.z += e2; den.w += e3;
        num.x = fmaf(e0, m.x * a, num.x);
        num.y = fmaf(e1, m.y * a, num.y);
        num.z = fmaf(e2, m.z * a, num.z);
        num.w = fmaf(e3, m.w * a, num.w);
    }
    // ---- pass 2B: uncached full groups (re-gather; rare) ----
    for (int it = RT1; it < nfull; it++) {
        int kk = it * 8 + e8;
        int s = sp[kk];
        float4 m = *(const float4*)(g_xl1 + s * 16 + q * 4);
        float a = g_p[node * CAP + kk] * rinv;
        float we = a * tl2e;
        float e0 = ex2f(m.x * we);
        float e1 = ex2f(m.y * we);
        float e2 = ex2f(m.z * we);
        float e3 = ex2f(m.w * we);
        den.x += e0; den.y += e1; den.z += e2; den.w += e3;
        num.x = fmaf(e0, m.x * a, num.x);
        num.y = fmaf(e1, m.y * a, num.y);
        num.z = fmaf(e2, m.z * a, num.z);
        num.w = fmaf(e3, m.w * a, num.w);
    }
    // ---- pass 2C: remainder ----
    if (rem) {
        int kk = nfull * 8 + e8;
        bool v = e8 < rem;
        float vm = v ? 1.f : 0.f;
        float4 m; float p;
        if (nfull < RT1) {
            m = make_float4(0.f, 0.f, 0.f, 0.f); p = 0.f;
#pragma unroll
            for (int j = 0; j < RT1; j++)
                if (j == nfull) { m = mreg[j]; p = preg[j]; }
        } else {
            m = make_float4(0.f, 0.f, 0.f, 0.f); p = 0.f;
            if (v) {
                m = *(const float4*)(g_xl1 + sp[kk] * 16 + q * 4);
                p = g_p[node * CAP + kk];
            }
        }
        float a = p * rinv;
        float we = a * tl2e;
        float e0 = ex2f(m.x * we) * vm;
        float e1 = ex2f(m.y * we) * vm;
        float e2 = ex2f(m.z * we) * vm;
        float e3 = ex2f(m.w * we) * vm;
        den.x += e0; den.y += e1; den.z += e2; den.w += e3;
        num.x = fmaf(e0, m.x * a, num.x);
        num.y = fmaf(e1, m.y * a, num.y);
        num.z = fmaf(e2, m.z * a, num.z);
        num.w = fmaf(e3, m.w * a, num.w);
    }
    // ---- pass 2: overflow list (cold) ----
    if (deg > CAP) {
        int ovfn = g_ovf_cnt;
        for (int i = 0; i < ovfn; i++) {
            if (g_ovfd[i] == node) {
                float4 m = make_float4(0.f, 0.f, 0.f, 0.f);
                if (e8 == 0) m = *(const float4*)(g_xl1 + g_ovfs[i] * 16 + q * 4);
                float y0 = m.x + xr.x, y1 = m.y + xr.y, y2 = m.z + xr.z, y3 = m.w + xr.w;
                float sc = a06x * y0;
                sc = fmaf(a04x, fabsf(y0), sc);
                sc = fmaf(a06y, y1, sc); sc = fmaf(a04y, fabsf(y1), sc);
                sc = fmaf(a06z, y2, sc); sc = fmaf(a04z, fabsf(y2), sc);
                sc = fmaf(a06w, y3, sc); sc = fmaf(a04w, fabsf(y3), sc);
                sc += __shfl_xor_sync(0xffffffffu, sc, 1);
                sc += __shfl_xor_sync(0xffffffffu, sc, 2);
                if (e8 == 0) {
                    float p = ex2f(sc);
                    float a = p * rinv;
                    float we = a * tl2e;
                    float e0 = ex2f(m.x * we);
                    float e1 = ex2f(m.y * we);
                    float e2 = ex2f(m.z * we);
                    float e3 = ex2f(m.w * we);
                    den.x += e0; den.y += e1; den.z += e2; den.w += e3;
                    num.x = fmaf(e0, m.x * a, num.x);
                    num.y = fmaf(e1, m.y * a, num.y);
                    num.z = fmaf(e2, m.z * a, num.z);
                    num.w = fmaf(e3, m.w * a, num.w);
                }
            }
        }
    }
#pragma unroll
    for (int o = 4; o < 32; o <<= 1) {
        num.x += __shfl_xor_sync(0xffffffffu, num.x, o);
        num.y += __shfl_xor_sync(0xffffffffu, num.y, o);
        num.z += __shfl_xor_sync(0xffffffffu, num.z, o);
        num.w += __shfl_xor_sync(0xffffffffu, num.w, o);
        den.x += __shfl_xor_sync(0xffffffffu, den.x, o);
        den.y += __shfl_xor_sync(0xffffffffu, den.y, o);
        den.z += __shfl_xor_sync(0xffffffffu, den.z, o);
        den.w += __shfl_xor_sync(0xffffffffu, den.w, o);
    }

    // ---- all lanes: h quad for own q, then fused layer-2 GEMM ----
    float4 b4 = *(const float4*)(bias + q * 4);
    float4 l4 = *(const float4*)(g_lin1 + node * 16 + q * 4);
    float4 o4;
    {
        float g0 = (den.x > 0.f) ? __fdividef(num.x, den.x) : 0.f;
        float g1 = (den.y > 0.f) ? __fdividef(num.y, den.y) : 0.f;
        float g2v = (den.z > 0.f) ? __fdividef(num.z, den.z) : 0.f;
        float g3 = (den.w > 0.f) ? __fdividef(num.w, den.w) : 0.f;
        o4.x = fmaxf(g0 + b4.x + l4.x, 0.f);
        o4.y = fmaxf(g1 + b4.y + l4.y, 0.f);
        o4.z = fmaxf(g2v + b4.z + l4.z, 0.f);
        o4.w = fmaxf(g3 + b4.w + l4.w, 0.f);
    }
    // lane j (<24) computes output column j of [xl2|xr2|lin2]
    float accj = 0.f;
#pragma unroll
    for (int kk2 = 0; kk2 < 16; kk2++) {
        float comp = (kk2 & 3) == 0 ? o4.x : (kk2 & 3) == 1 ? o4.y
                   : (kk2 & 3) == 2 ? o4.z : o4.w;
        float hk = __shfl_sync(0xffffffffu, comp, kk2 >> 2);
        accj = fmaf(hk, s_w2[kk2 * 24 + lane < 16 * 24 ? kk2 * 24 + (lane & 31) : 0], accj);
    }
    if (lane < 24) {
        if (lane < 8)       g_xl2[node * 8 + lane] = accj;
        else if (lane < 16) g_xr2[node * 8 + lane - 8] = accj;
        else                g_lin2[node * 8 + lane - 16] = accj + s_b2[lane - 16];
    }
}

// ------- edge kernel layer 2 (2 lanes/edge) + fused MLP head + log_sigmoid --
__global__ void __launch_bounds__(256) k_edge2h(
    const float* __restrict__ att, const float* __restrict__ bias,
    const float* __restrict__ tptr,
    const float* __restrict__ W3, const float* __restrict__ b3,
    const float* __restrict__ W4, const float* __restrict__ b4,
    const float* __restrict__ W5, const float* __restrict__ b5,
    const float* __restrict__ Wout, const float* __restrict__ bout,
    float* __restrict__ out)
{
    if (blockIdx.x == 0 && threadIdx.x == 0) g_ovf_cnt = 0;  // next-call reset
    int w = threadIdx.x >> 5;
    int lane = threadIdx.x & 31;
    int node = blockIdx.x * 8 + w;
    if (node >= NN) return;
    int q = lane & 1, e16 = lane >> 1;
    int deg = g_cnt[node];
    if (lane == 0) g_cnt[node] = 0;   // reset for next launch
    int degf = deg < CAP ? deg : CAP;
    const int* sp = g_srcs + node * CAP;
    float tl2e = tptr[0] * L2E;
    float4 a4 = *(const float4*)(att + q * 4);
    float4 xr = *(const float4*)(g_xr2 + node * 8 + q * 4);
    float a06x = 0.6f * L2E * a4.x, a06y = 0.6f * L2E * a4.y;
    float a06z = 0.6f * L2E * a4.z, a06w = 0.6f * L2E * a4.w;
    float a04x = 0.4f * L2E * a4.x, a04y = 0.4f * L2E * a4.y;
    float a04z = 0.4f * L2E * a4.z, a04w = 0.4f * L2E * a4.w;
    int nfull = degf >> 4, rem = degf & 15;
    int itc = nfull < RT2 ? nfull : RT2;

    float4 mreg[RT2];
    float  preg[RT2];

    float S = 0.f;
#pragma unroll
    for (int it = 0; it < RT2; it++) {
        if (it >= itc) break;
        int kk = it * 16 + e16;
        int s = sp[kk];
        float4 m = *(const float4*)(g_xl2 + s * 8 + q * 4);
        float y0 = m.x + xr.x, y1 = m.y + xr.y, y2 = m.z + xr.z, y3 = m.w + xr.w;
        float sc = a06x * y0;
        sc = fmaf(a04x, fabsf(y0), sc);
        sc = fmaf(a06y, y1, sc); sc = fmaf(a04y, fabsf(y1), sc);
        sc = fmaf(a06z, y2, sc); sc = fmaf(a04z, fabsf(y2), sc);
        sc = fmaf(a06w, y3, sc); sc = fmaf(a04w, fabsf(y3), sc);
        sc += __shfl_xor_sync(0xffffffffu, sc, 1);
        float p = ex2f(sc);
        mreg[it] = m; preg[it] = p;
        S += p;
    }
    for (int it = RT2; it < nfull; it++) {
        int kk = it * 16 + e16;
        int s = sp[kk];
        float4 m = *(const float4*)(g_xl2 + s * 8 + q * 4);
        float y0 = m.x + xr.x, y1 = m.y + xr.y, y2 = m.z + xr.z, y3 = m.w + xr.w;
        float sc = a06x * y0;
        sc = fmaf(a04x, fabsf(y0), sc);
        sc = fmaf(a06y, y1, sc); sc = fmaf(a04y, fabsf(y1), sc);
        sc = fmaf(a06z, y2, sc); sc = fmaf(a04z, fabsf(y2), sc);
        sc = fmaf(a06w, y3, sc); sc = fmaf(a04w, fabsf(y3), sc);
        sc += __shfl_xor_sync(0xffffffffu, sc, 1);
        float p = ex2f(sc);
        g_p[node * CAP + kk] = p;
        S += p;
    }
    if (rem) {
        int kk = nfull * 16 + e16;
        bool v = e16 < rem;
        float4 m = make_float4(0.f, 0.f, 0.f, 0.f);
        if (v) m = *(const float4*)(g_xl2 + sp[kk] * 8 + q * 4);
        float y0 = m.x + xr.x, y1 = m.y + xr.y, y2 = m.z + xr.z, y3 = m.w + xr.w;
        float sc = a06x * y0;
        sc = fmaf(a04x, fabsf(y0), sc);
        sc = fmaf(a06y, y1, sc); sc = fmaf(a04y, fabsf(y1), sc);
        sc = fmaf(a06z, y2, sc); sc = fmaf(a04z, fabsf(y2), sc);
        sc = fmaf(a06w, y3, sc); sc = fmaf(a04w, fabsf(y3), sc);
        sc += __shfl_xor_sync(0xffffffffu, sc, 1);
        float p = v ? ex2f(sc) : 0.f;
        if (nfull < RT2) {
#pragma unroll
            for (int j = 0; j < RT2; j++)
                if (j == nfull) { mreg[j] = m; preg[j] = p; }
        } else {
            g_p[node * CAP + kk] = p;
        }
        S += p;
    }
    if (deg > CAP) {
        int ovfn = g_ovf_cnt2;
        for (int i = 0; i < ovfn; i++) {
            if (g_ovfd[i] == node) {
                float4 m = make_float4(0.f, 0.f, 0.f, 0.f);
                if (e16 == 0) m = *(const float4*)(g_xl2 + g_ovfs[i] * 8 + q * 4);
                float y0 = m.x + xr.x, y1 = m.y + xr.y, y2 = m.z + xr.z, y3 = m.w + xr.w;
                float sc = a06x * y0;
                sc = fmaf(a04x, fabsf(y0), sc);
                sc = fmaf(a06y, y1, sc); sc = fmaf(a04y, fabsf(y1), sc);
                sc = fmaf(a06z, y2, sc); sc = fmaf(a04z, fabsf(y2), sc);
                sc = fmaf(a04w, fabsf(y3), fmaf(a06w, y3, sc));
                sc += __shfl_xor_sync(0xffffffffu, sc, 1);
                if (e16 == 0) S += ex2f(sc);
            }
        }
    }
#pragma unroll
    for (int o = 16; o; o >>= 1) S += __shfl_xor_sync(0xffffffffu, S, o);
    float rinv = __fdividef(2.f, S);   // S counted 2x per edge
    __syncwarp();

    float4 num = make_float4(0.f, 0.f, 0.f, 0.f);
    float4 den = make_float4(0.f, 0.f, 0.f, 0.f);
#pragma unroll
    for (int it = 0; it < RT2; it++) {
        if (it >= itc) break;
        float4 m = mreg[it];
        float a = preg[it] * rinv;
        float we = a * tl2e;
        float e0 = ex2f(m.x * we);
        float e1 = ex2f(m.y * we);
        float e2 = ex2f(m.z * we);
        float e3 = ex2f(m.w * we);
        den.x += e0; den.y += e1; den.z += e2; den.w += e3;
        num.x = fmaf(e0, m.x * a, num.x);
        num.y = fmaf(e1, m.y * a, num.y);
        num.z = fmaf(e2, m.z * a, num.z);
        num.w = fmaf(e3, m.w * a, num.w);
    }
    for (int it = RT2; it < nfull; it++) {
        int kk = it * 16 + e16;
        int s = sp[kk];
        float4 m = *(const float4*)(g_xl2 + s * 8 + q * 4);
        float a = g_p[node * CAP + kk] * rinv;
        float we = a * tl2e;
        float e0 = ex2f(m.x * we);
        float e1 = ex2f(m.y * we);
        float e2 = ex2f(m.z * we);
        float e3 = ex2f(m.w * we);
        den.x += e0; den.y += e1; den.z += e2; den.w += e3;
        num.x = fmaf(e0, m.x * a, num.x);
        num.y = fmaf(e1, m.y * a, num.y);
        num.z = fmaf(e2, m.z * a, num.z);
        num.w = fmaf(e3, m.w * a, num.w);
    }
    if (rem) {
        int kk = nfull * 16 + e16;
        bool v = e16 < rem;
        float vm = v ? 1.f : 0.f;
        float4 m; float p;
        if (nfull < RT2) {
            m = make_float4(0.f, 0.f, 0.f, 0.f); p = 0.f;
#pragma unroll
            for (int j = 0; j < RT2; j++)
                if (j == nfull) { m = mreg[j]; p = preg[j]; }
        } else {
            m = make_float4(0.f, 0.f, 0.f, 0.f); p = 0.f;
            if (v) {
                m = *(const float4*)(g_xl2 + sp[kk] * 8 + q * 4);
                p = g_p[node * CAP + kk];
            }
        }
        float a = p * rinv;
        float we = a * tl2e;
        float e0 = ex2f(m.x * we) * vm;
        float e1 = ex2f(m.y * we) * vm;
        float e2 = ex2f(m.z * we) * vm;
        float e3 = ex2f(m.w * we) * vm;
        den.x += e0; den.y += e1; den.z += e2; den.w += e3;
        num.x = fmaf(e0, m.x * a, num.x);
        num.y = fmaf(e1, m.y * a, num.y);
        num.z = fmaf(e2, m.z * a, num.z);
        num.w = fmaf(e3, m.w * a, num.w);
    }
    if (deg > CAP) {
        int ovfn = g_ovf_cnt2;
        for (int i = 0; i < ovfn; i++) {
            if (g_ovfd[i] == node) {
                float4 m = make_float4(0.f, 0.f, 0.f, 0.f);
                if (e16 == 0) m = *(const float4*)(g_xl2 + g_ovfs[i] * 8 + q * 4);
                float y0 = m.x + xr.x, y1 = m.y + xr.y, y2 = m.z + xr.z, y3 = m.w + xr.w;
                float sc = a06x * y0;
                sc = fmaf(a04x, fabsf(y0), sc);
                sc = fmaf(a06y, y1, sc); sc = fmaf(a04y, fabsf(y1), sc);
                sc = fmaf(a06z, y2, sc); sc = fmaf(a04z, fabsf(y2), sc);
                sc = fmaf(a04w, fabsf(y3), fmaf(a06w, y3, sc));
                sc += __shfl_xor_sync(0xffffffffu, sc, 1);
                if (e16 == 0) {
                    float p = ex2f(sc);
                    float a = p * rinv;
                    float we = a * tl2e;
                    float e0 = ex2f(m.x * we);
                    float e1 = ex2f(m.y * we);
                    float e2 = ex2f(m.z * we);
                    float e3 = ex2f(m.w * we);
                    den.x += e0; den.y += e1; den.z += e2; den.w += e3;
                    num.x = fmaf(e0, m.x * a, num.x);
                    num.y = fmaf(e1, m.y * a, num.y);
                    num.z = fmaf(e2, m.z * a, num.z);
                    num.w = fmaf(e3, m.w * a, num.w);
                }
            }
        }
    }
#pragma unroll
    for (int o = 2; o < 32; o <<= 1) {
        num.x += __shfl_xor_sync(0xffffffffu, num.x, o);
        num.y += __shfl_xor_sync(0xffffffffu, num.y, o);
        num.z += __shfl_xor_sync(0xffffffffu, num.z, o);
        num.w += __shfl_xor_sync(0xffffffffu, num.w, o);
        den.x += __shfl_xor_sync(0xffffffffu, den.x, o);
        den.y += __shfl_xor_sync(0xffffffffu, den.y, o);
        den.z += __shfl_xor_sync(0xffffffffu, den.z, o);
        den.w += __shfl_xor_sync(0xffffffffu, den.w, o);
    }

    // ---- fused head: lanes pair via q ----
    float4 b4v = *(const float4*)(bias + q * 4);
    float4 l4 = *(const float4*)(g_lin2 + node * 8 + q * 4);
    float hq[4];
    {
        float g0 = (den.x > 0.f) ? __fdividef(num.x, den.x) : 0.f;
        float g1 = (den.y > 0.f) ? __fdividef(num.y, den.y) : 0.f;
        float g2v = (den.z > 0.f) ? __fdividef(num.z, den.z) : 0.f;
        float g3 = (den.w > 0.f) ? __fdividef(num.w, den.w) : 0.f;
        hq[0] = fmaxf(g0 + b4v.x + l4.x, 0.f);
        hq[1] = fmaxf(g1 + b4v.y + l4.y, 0.f);
        hq[2] = fmaxf(g2v + b4v.z + l4.z, 0.f);
        hq[3] = fmaxf(g3 + b4v.w + l4.w, 0.f);
    }
    float part[8];
#pragma unroll
    for (int c = 0; c < 8; c++) {
        float acc = 0.f;
#pragma unroll
        for (int j = 0; j < 4; j++)
            acc = fmaf(hq[j], W3[(4 * q + j) * 8 + c], acc);
        part[c] = acc;
    }
#pragma unroll
    for (int c = 0; c < 8; c++)
        part[c] += __shfl_xor_sync(0xffffffffu, part[c], 1);
    if (lane == 0) {
        float s4 = b4[0];
#pragma unroll
        for (int c = 0; c < 8; c++) {
            float z = part[c] + b3[c];
            z = z > 0.f ? z : 0.f;
            s4 = fmaf(z, W4[c], s4);
        }
        s4 = s4 > 0.f ? s4 : 0.f;
        float s5 = W5[0] * s4 + b5[0];
        s5 = s5 > 0.f ? s5 : 0.f;
        float xo = Wout[0] * s5 + bout[0];
        float ls = (xo >= 0.f) ? -log1pf(expf(-xo)) : (xo - log1pf(expf(xo)));
        out[node] = ls;
    }
}

// ---------------- launch ----------------
extern "C" void kernel_launch(void* const* d_in, const int* in_sizes, int n_in,
                              void* d_out, int out_size)
{
    const float* x    = (const float*)d_in[0];
    const int*   ei   = (const int*)d_in[1];
    const int*   src  = ei;
    const int*   dst  = ei + EE;
    const float* Wl1  = (const float*)d_in[3];
    const float* Wr1  = (const float*)d_in[4];
    const float* att1 = (const float*)d_in[5];
    const float* b1   = (const float*)d_in[6];
    const float* Wlin1= (const float*)d_in[7];
    const float* blin1= (const float*)d_in[8];
    const float* Wl2  = (const float*)d_in[9];
    const float* Wr2  = (const float*)d_in[10];
    const float* att2 = (const float*)d_in[11];
    const float* b2   = (const float*)d_in[12];
    const float* Wlin2= (const float*)d_in[13];
    const float* blin2= (const float*)d_in[14];
    const float* t    = (const float*)d_in[15];
    const float* W3   = (const float*)d_in[16];
    const float* b3   = (const float*)d_in[17];
    const float* W4   = (const float*)d_in[18];
    const float* b4   = (const float*)d_in[19];
    const float* W5   = (const float*)d_in[20];
    const float* b5   = (const float*)d_in[21];
    const float* Wout = (const float*)d_in[22];
    const float* bout = (const float*)d_in[23];
    float* out = (float*)d_out;

    // 0: fused layer-1 GEMM + direct bucket scatter
    k_build<<<GEMM1_BLKS + HIST_BLKS, 128>>>(src, dst, x, Wl1, Wr1, Wlin1, blin1);
    // 1: edge layer 1 + fused layer-2 node GEMM
    k_edge1<<<(NN + 7) / 8, 256>>>(att1, b1, t, Wl2, Wr2, Wlin2, blin2);
    // 2: edge layer 2 + fused MLP head
    k_edge2h<<<(NN + 7) / 8, 256>>>(att2, b2, t, W3, b3, W4, b4, W5, b5, Wout, bout, out);
}

// round 8
// speedup vs baseline: 1.1167x; 1.1167x over previous
#include <cuda_runtime.h>

#define NN 100000
#define EE 3200000
#define FIN 128
#define CAP 128                // fixed bucket capacity per node
#define GEMM1_BLKS 782         // ceil(NN/128)
#define HIST_BLKS 12500        // ceil(EE/256)
#define L2E 1.44269504f

// ---------------- scratch (static device globals; no allocs) ----------------
__device__ int   g_cnt[NN];          // zero at load; re-zeroed by k_edge2h
__device__ int   g_srcs[NN * CAP];   // fixed-capacity CSR buckets
__device__ int   g_ovf_cnt;          // overflow count (build writes)
__device__ int   g_ovf_cnt2;         // snapshot (edge1 writes, edge2h reads)
__device__ int   g_ovfd[EE];         // overflow dst (cold)
__device__ int   g_ovfs[EE];         // overflow src (cold)
__device__ float g_xl1[NN * 16];
__device__ float g_xr1[NN * 16];
__device__ float g_lin1[NN * 16];
__device__ float g_xl2[NN * 8];
__device__ float g_xr2[NN * 8];
__device__ float g_lin2[NN * 8];

__device__ __forceinline__ float ex2f(float x) {
    float y; asm("ex2.approx.f32 %0, %1;" : "=f"(y) : "f"(x)); return y;
}

// ---- fused build: layer-1 GEMM (blocks 0..781) + bucket scatter (rest) -----
__global__ void __launch_bounds__(256) k_build(
    const int* __restrict__ src, const int* __restrict__ dst,
    const float* __restrict__ x, const float* __restrict__ Wl,
    const float* __restrict__ Wr, const float* __restrict__ Wlin,
    const float* __restrict__ blin)
{
    __shared__ float sx[128][36];
    __shared__ float sw[32][48];
    int t = threadIdx.x;
    int b = blockIdx.x;

    if (b >= GEMM1_BLKS) {
        int e = (b - GEMM1_BLKS) * 256 + t;
        if (e < EE) {
            int d = dst[e];
            int r = atomicAdd(&g_cnt[d], 1);
            if (r < CAP) {
                g_srcs[d * CAP + r] = src[e];
            } else {
                int o = atomicAdd(&g_ovf_cnt, 1);
                g_ovfd[o] = d;
                g_ovfs[o] = src[e];
            }
        }
        return;
    }

    // ---- gemm1: 128 rows x 48 cols; thread: 4 rows x 6 cols; K tile 32 ----
    int cg = t & 7, rg = t >> 3;
    int c0 = cg * 6;
    int rowbase = b * 128;
    float acc[4][6];
#pragma unroll
    for (int i = 0; i < 4; i++)
#pragma unroll
        for (int j = 0; j < 6; j++) acc[i][j] = 0.f;

    for (int kb = 0; kb < FIN; kb += 32) {
#pragma unroll
        for (int n = 0; n < 4; n++) {
            int idx = t + n * 256;
            int r = idx >> 3, k4 = idx & 7;
            int gr = rowbase + r;
            float4 val = make_float4(0.f, 0.f, 0.f, 0.f);
            if (gr < NN) val = *(const float4*)(x + gr * FIN + kb + k4 * 4);
            *(float4*)&sx[r][k4 * 4] = val;
        }
        for (int idx = t; idx < 32 * 48; idx += 256) {
            int k = idx / 48, j = idx % 48;
            int gk = kb + k;
            float val;
            if (j < 16)      val = Wl[gk * 16 + j];
            else if (j < 32) val = Wr[gk * 16 + j - 16];
            else             val = Wlin[gk * 16 + j - 32];
            sw[k][j] = val;
        }
        __syncthreads();
#pragma unroll
        for (int k = 0; k < 32; k += 4) {
            float xv[4][4];
#pragma unroll
            for (int i = 0; i < 4; i++) {
                float4 tmp = *(const float4*)&sx[rg * 4 + i][k];
                xv[i][0] = tmp.x; xv[i][1] = tmp.y; xv[i][2] = tmp.z; xv[i][3] = tmp.w;
            }
#pragma unroll
            for (int kk = 0; kk < 4; kk++) {
                float wv[6];
#pragma unroll
                for (int j = 0; j < 6; j++) wv[j] = sw[k + kk][c0 + j];
#pragma unroll
                for (int i = 0; i < 4; i++)
#pragma unroll
                    for (int j = 0; j < 6; j++)
                        acc[i][j] = fmaf(xv[i][kk], wv[j], acc[i][j]);
            }
        }
        __syncthreads();
    }
#pragma unroll
    for (int i = 0; i < 4; i++) {
        int gr = rowbase + rg * 4 + i;
        if (gr < NN) {
#pragma unroll
            for (int j = 0; j < 6; j++) {
                int c = c0 + j;
                if (c < 16)      g_xl1[gr * 16 + c] = acc[i][j];
                else if (c < 32) g_xr1[gr * 16 + (c - 16)] = acc[i][j];
                else             g_lin1[gr * 16 + (c - 32)] = acc[i][j] + blin[c - 32];
            }
        }
    }
}

// ------ edge layer 1 (4 lanes/edge) + fused layer-2 node GEMM epilogue ------
__global__ void __launch_bounds__(256) k_edge1(
    const float* __restrict__ att, const float* __restrict__ bias,
    const float* __restrict__ tptr,
    const float* __restrict__ Wl2, const float* __restrict__ Wr2,
    const float* __restrict__ Wlin2, const float* __restrict__ blin2)
{
    __shared__ float sm_p[8][CAP];
    __shared__ float s_w2[16 * 24];
    __shared__ float s_b2[8];
    {
        int t = threadIdx.x;
        for (int idx = t; idx < 16 * 24; idx += 256) {
            int k = idx / 24, j = idx % 24;
            float v;
            if (j < 8)       v = Wl2[k * 8 + j];
            else if (j < 16) v = Wr2[k * 8 + j - 8];
            else             v = Wlin2[k * 8 + j - 16];
            s_w2[idx] = v;
        }
        if (t < 8) s_b2[t] = blin2[t];
        if (blockIdx.x == 0 && t == 0) g_ovf_cnt2 = g_ovf_cnt;
    }
    __syncthreads();

    int w = threadIdx.x >> 5;
    int lane = threadIdx.x & 31;
    int node = blockIdx.x * 8 + w;
    if (node >= NN) return;
    int q = lane & 3, e8 = lane >> 2;
    int deg = g_cnt[node];
    int degf = deg < CAP ? deg : CAP;
    const int* sp = g_srcs + node * CAP;
    float tl2e = tptr[0] * L2E;
    float4 a4 = *(const float4*)(att + q * 4);
    float4 xr = *(const float4*)(g_xr1 + node * 16 + q * 4);
    float a06x = 0.6f * L2E * a4.x, a06y = 0.6f * L2E * a4.y;
    float a06z = 0.6f * L2E * a4.z, a06w = 0.6f * L2E * a4.w;
    float a04x = 0.4f * L2E * a4.x, a04y = 0.4f * L2E * a4.y;
    float a04z = 0.4f * L2E * a4.z, a04w = 0.4f * L2E * a4.w;
    int nfull = degf >> 3, rem = degf & 7;

    // ---- pass 1: scores -> p (cached in smem), accumulate S ----
    float S = 0.f;
    int k = e8;
#pragma unroll 2
    for (int it = 0; it < nfull; it++, k += 8) {
        int s = sp[k];
        float4 m = *(const float4*)(g_xl1 + s * 16 + q * 4);
        float y0 = m.x + xr.x, y1 = m.y + xr.y, y2 = m.z + xr.z, y3 = m.w + xr.w;
        float sc = a06x * y0;
        sc = fmaf(a04x, fabsf(y0), sc);
        sc = fmaf(a06y, y1, sc); sc = fmaf(a04y, fabsf(y1), sc);
        sc = fmaf(a06z, y2, sc); sc = fmaf(a04z, fabsf(y2), sc);
        sc = fmaf(a06w, y3, sc); sc = fmaf(a04w, fabsf(y3), sc);
        sc += __shfl_xor_sync(0xffffffffu, sc, 1);
        sc += __shfl_xor_sync(0xffffffffu, sc, 2);
        float p = ex2f(sc);
        if (q == 0) sm_p[w][k] = p;
        S += p;
    }
    if (rem) {
        bool v = e8 < rem;
        int s = sp[v ? k : 0];
        float4 m = make_float4(0.f, 0.f, 0.f, 0.f);
        if (v) m = *(const float4*)(g_xl1 + s * 16 + q * 4);
        float y0 = m.x + xr.x, y1 = m.y + xr.y, y2 = m.z + xr.z, y3 = m.w + xr.w;
        float sc = a06x * y0;
        sc = fmaf(a04x, fabsf(y0), sc);
        sc = fmaf(a06y, y1, sc); sc = fmaf(a04y, fabsf(y1), sc);
        sc = fmaf(a06z, y2, sc); sc = fmaf(a04z, fabsf(y2), sc);
        sc = fmaf(a06w, y3, sc); sc = fmaf(a04w, fabsf(y3), sc);
        sc += __shfl_xor_sync(0xffffffffu, sc, 1);
        sc += __shfl_xor_sync(0xffffffffu, sc, 2);
        float p = v ? ex2f(sc) : 0.f;
        if (q == 0) sm_p[w][k] = p;
        S += p;
    }
    // ---- pass 1: overflow list (cold) ----
    if (deg > CAP) {
        int ovfn = g_ovf_cnt;
        for (int i = 0; i < ovfn; i++) {
            if (g_ovfd[i] == node) {
                float4 m = make_float4(0.f, 0.f, 0.f, 0.f);
                if (e8 == 0) m = *(const float4*)(g_xl1 + g_ovfs[i] * 16 + q * 4);
                float y0 = m.x + xr.x, y1 = m.y + xr.y, y2 = m.z + xr.z, y3 = m.w + xr.w;
                float sc = a06x * y0;
                sc = fmaf(a04x, fabsf(y0), sc);
                sc = fmaf(a06y, y1, sc); sc = fmaf(a04y, fabsf(y1), sc);
                sc = fmaf(a06z, y2, sc); sc = fmaf(a04z, fabsf(y2), sc);
                sc = fmaf(a06w, y3, sc); sc = fmaf(a04w, fabsf(y3), sc);
                sc += __shfl_xor_sync(0xffffffffu, sc, 1);
                sc += __shfl_xor_sync(0xffffffffu, sc, 2);
                if (e8 == 0) S += ex2f(sc);
            }
        }
    }
#pragma unroll
    for (int o = 16; o; o >>= 1) S += __shfl_xor_sync(0xffffffffu, S, o);
    float rinv = __fdividef(4.f, S);   // S counted 4x per edge
    __syncwarp();

    // ---- pass 2: re-gather (L1-hot) + fused softmax-agg num/den ----
    float4 num = make_float4(0.f, 0.f, 0.f, 0.f);
    float4 den = make_float4(0.f, 0.f, 0.f, 0.f);
    k = e8;
#pragma unroll 2
    for (int it = 0; it < nfull; it++, k += 8) {
        int s = sp[k];
        float4 m = *(const float4*)(g_xl1 + s * 16 + q * 4);
        float p = sm_p[w][k];
        float a = p * rinv;
        float we = a * tl2e;
        float e0 = ex2f(m.x * we);
        float e1 = ex2f(m.y * we);
        float e2 = ex2f(m.z * we);
        float e3 = ex2f(m.w * we);
        den.x += e0; den.y += e1; den.z += e2; den.w += e3;
        num.x = fmaf(e0, m.x * a, num.x);
        num.y = fmaf(e1, m.y * a, num.y);
        num.z = fmaf(e2, m.z * a, num.z);
        num.w = fmaf(e3, m.w * a, num.w);
    }
    if (rem) {
        bool v = e8 < rem;
        float vm = v ? 1.f : 0.f;
        int s = sp[v ? k : 0];
        float4 m = make_float4(0.f, 0.f, 0.f, 0.f);
        if (v) m = *(const float4*)(g_xl1 + s * 16 + q * 4);
        float p = sm_p[w][k];
        float a = p * rinv;
        float we = a * tl2e;
        float e0 = ex2f(m.x * we) * vm;
        float e1 = ex2f(m.y * we) * vm;
        float e2 = ex2f(m.z * we) * vm;
        float e3 = ex2f(m.w * we) * vm;
        den.x += e0; den.y += e1; den.z += e2; den.w += e3;
        num.x = fmaf(e0, m.x * a, num.x);
        num.y = fmaf(e1, m.y * a, num.y);
        num.z = fmaf(e2, m.z * a, num.z);
        num.w = fmaf(e3, m.w * a, num.w);
    }
    // ---- pass 2: overflow list (cold) ----
    if (deg > CAP) {
        int ovfn = g_ovf_cnt;
        for (int i = 0; i < ovfn; i++) {
            if (g_ovfd[i] == node) {
                float4 m = make_float4(0.f, 0.f, 0.f, 0.f);
                if (e8 == 0) m = *(const float4*)(g_xl1 + g_ovfs[i] * 16 + q * 4);
                float y0 = m.x + xr.x, y1 = m.y + xr.y, y2 = m.z + xr.z, y3 = m.w + xr.w;
                float sc = a06x * y0;
                sc = fmaf(a04x, fabsf(y0), sc);
                sc = fmaf(a06y, y1, sc); sc = fmaf(a04y, fabsf(y1), sc);
                sc = fmaf(a06z, y2, sc); sc = fmaf(a04z, fabsf(y2), sc);
                sc = fmaf(a06w, y3, sc); sc = fmaf(a04w, fabsf(y3), sc);
                sc += __shfl_xor_sync(0xffffffffu, sc, 1);
                sc += __shfl_xor_sync(0xffffffffu, sc, 2);
                if (e8 == 0) {
                    float p = ex2f(sc);
                    float a = p * rinv;
                    float we = a * tl2e;
                    float e0 = ex2f(m.x * we);
                    float e1 = ex2f(m.y * we);
                    float e2 = ex2f(m.z * we);
                    float e3 = ex2f(m.w * we);
                    den.x += e0; den.y += e1; den.z += e2; den.w += e3;
                    num.x = fmaf(e0, m.x * a, num.x);
                    num.y = fmaf(e1, m.y * a, num.y);
                    num.z = fmaf(e2, m.z * a, num.z);
                    num.w = fmaf(e3, m.w * a, num.w);
                }
            }
        }
    }
#pragma unroll
    for (int o = 4; o < 32; o <<= 1) {
        num.x += __shfl_xor_sync(0xffffffffu, num.x, o);
        num.y += __shfl_xor_sync(0xffffffffu, num.y, o);
        num.z += __shfl_xor_sync(0xffffffffu, num.z, o);
        num.w += __shfl_xor_sync(0xffffffffu, num.w, o);
        den.x += __shfl_xor_sync(0xffffffffu, den.x, o);
        den.y += __shfl_xor_sync(0xffffffffu, den.y, o);
        den.z += __shfl_xor_sync(0xffffffffu, den.z, o);
        den.w += __shfl_xor_sync(0xffffffffu, den.w, o);
    }

    // ---- all lanes compute h quad for own q, then fused layer-2 GEMM ----
    float4 b4 = *(const float4*)(bias + q * 4);
    float4 l4 = *(const float4*)(g_lin1 + node * 16 + q * 4);
    float4 o4;
    {
        float g0 = (den.x > 0.f) ? __fdividef(num.x, den.x) : 0.f;
        float g1 = (den.y > 0.f) ? __fdividef(num.y, den.y) : 0.f;
        float g2v = (den.z > 0.f) ? __fdividef(num.z, den.z) : 0.f;
        float g3 = (den.w > 0.f) ? __fdividef(num.w, den.w) : 0.f;
        o4.x = fmaxf(g0 + b4.x + l4.x, 0.f);
        o4.y = fmaxf(g1 + b4.y + l4.y, 0.f);
        o4.z = fmaxf(g2v + b4.z + l4.z, 0.f);
        o4.w = fmaxf(g3 + b4.w + l4.w, 0.f);
    }
    // lane j (<24) computes output column j of h[16] x W2cat[16x24]
    int col = lane < 24 ? lane : 0;
    float accj = 0.f;
#pragma unroll
    for (int k2 = 0; k2 < 16; k2++) {
        float comp = ((k2 & 3) == 0) ? o4.x : ((k2 & 3) == 1) ? o4.y
                   : ((k2 & 3) == 2) ? o4.z : o4.w;
        float hk = __shfl_sync(0xffffffffu, comp, k2 >> 2);
        accj = fmaf(hk, s_w2[k2 * 24 + col], accj);
    }
    if (lane < 8)       g_xl2[node * 8 + lane] = accj;
    else if (lane < 16) g_xr2[node * 8 + lane - 8] = accj;
    else if (lane < 24) g_lin2[node * 8 + lane - 16] = accj + s_b2[lane - 16];
}

// ------- edge kernel layer 2 (2 lanes/edge) + fused MLP head + log_sigmoid --
__global__ void __launch_bounds__(256) k_edge2h(
    const float* __restrict__ att, const float* __restrict__ bias,
    const float* __restrict__ tptr,
    const float* __restrict__ W3, const float* __restrict__ b3,
    const float* __restrict__ W4, const float* __restrict__ b4,
    const float* __restrict__ W5, const float* __restrict__ b5,
    const float* __restrict__ Wout, const float* __restrict__ bout,
    float* __restrict__ out)
{
    __shared__ float sm_p[8][CAP];
    if (blockIdx.x == 0 && threadIdx.x == 0) g_ovf_cnt = 0;  // next-call reset
    int w = threadIdx.x >> 5;
    int lane = threadIdx.x & 31;
    int node = blockIdx.x * 8 + w;
    if (node >= NN) return;
    int q = lane & 1, e16 = lane >> 1;
    int deg = g_cnt[node];
    if (lane == 0) g_cnt[node] = 0;   // reset for next launch
    int degf = deg < CAP ? deg : CAP;
    const int* sp = g_srcs + node * CAP;
    float tl2e = tptr[0] * L2E;
    float4 a4 = *(const float4*)(att + q * 4);
    float4 xr = *(const float4*)(g_xr2 + node * 8 + q * 4);
    float a06x = 0.6f * L2E * a4.x, a06y = 0.6f * L2E * a4.y;
    float a06z = 0.6f * L2E * a4.z, a06w = 0.6f * L2E * a4.w;
    float a04x = 0.4f * L2E * a4.x, a04y = 0.4f * L2E * a4.y;
    float a04z = 0.4f * L2E * a4.z, a04w = 0.4f * L2E * a4.w;
    int nfull = degf >> 4, rem = degf & 15;

    float S = 0.f;
    int k = e16;
#pragma unroll 2
    for (int it = 0; it < nfull; it++, k += 16) {
        int s = sp[k];
        float4 m = *(const float4*)(g_xl2 + s * 8 + q * 4);
        float y0 = m.x + xr.x, y1 = m.y + xr.y, y2 = m.z + xr.z, y3 = m.w + xr.w;
        float sc = a06x * y0;
        sc = fmaf(a04x, fabsf(y0), sc);
        sc = fmaf(a06y, y1, sc); sc = fmaf(a04y, fabsf(y1), sc);
        sc = fmaf(a06z, y2, sc); sc = fmaf(a04z, fabsf(y2), sc);
        sc = fmaf(a06w, y3, sc); sc = fmaf(a04w, fabsf(y3), sc);
        sc += __shfl_xor_sync(0xffffffffu, sc, 1);
        float p = ex2f(sc);
        if (q == 0) sm_p[w][k] = p;
        S += p;
    }
    if (rem) {
        bool v = e16 < rem;
        int s = sp[v ? k : 0];
        float4 m = make_float4(0.f, 0.f, 0.f, 0.f);
        if (v) m = *(const float4*)(g_xl2 + s * 8 + q * 4);
        float y0 = m.x + xr.x, y1 = m.y + xr.y, y2 = m.z + xr.z, y3 = m.w + xr.w;
        float sc = a06x * y0;
        sc = fmaf(a04x, fabsf(y0), sc);
        sc = fmaf(a06y, y1, sc); sc = fmaf(a04y, fabsf(y1), sc);
        sc = fmaf(a06z, y2, sc); sc = fmaf(a04z, fabsf(y2), sc);
        sc = fmaf(a06w, y3, sc); sc = fmaf(a04w, fabsf(y3), sc);
        sc += __shfl_xor_sync(0xffffffffu, sc, 1);
        float p = v ? ex2f(sc) : 0.f;
        if (q == 0) sm_p[w][k] = p;
        S += p;
    }
    if (deg > CAP) {
        int ovfn = g_ovf_cnt2;
        for (int i = 0; i < ovfn; i++) {
            if (g_ovfd[i] == node) {
                float4 m = make_float4(0.f, 0.f, 0.f, 0.f);
                if (e16 == 0) m = *(const float4*)(g_xl2 + g_ovfs[i] * 8 + q * 4);
                float y0 = m.x + xr.x, y1 = m.y + xr.y, y2 = m.z + xr.z, y3 = m.w + xr.w;
                float sc = a06x * y0;
                sc = fmaf(a04x, fabsf(y0), sc);
                sc = fmaf(a06y, y1, sc); sc = fmaf(a04y, fabsf(y1), sc);
                sc = fmaf(a06z, y2, sc); sc = fmaf(a04z, fabsf(y2), sc);
                sc = fmaf(a06w, y3, sc); sc = fmaf(a04w, fabsf(y3), sc);
                sc += __shfl_xor_sync(0xffffffffu, sc, 1);
                if (e16 == 0) S += ex2f(sc);
            }
        }
    }
#pragma unroll
    for (int o = 16; o; o >>= 1) S += __shfl_xor_sync(0xffffffffu, S, o);
    float rinv = __fdividef(2.f, S);   // S counted 2x per edge
    __syncwarp();

    float4 num = make_float4(0.f, 0.f, 0.f, 0.f);
    float4 den = make_float4(0.f, 0.f, 0.f, 0.f);
    k = e16;
#pragma unroll 2
    for (int it = 0; it < nfull; it++, k += 16) {
        int s = sp[k];
        float4 m = *(const float4*)(g_xl2 + s * 8 + q * 4);
        float p = sm_p[w][k];
        float a = p * rinv;
        float we = a * tl2e;
        float e0 = ex2f(m.x * we);
        float e1 = ex2f(m.y * we);
        float e2 = ex2f(m.z * we);
        float e3 = ex2f(m.w * we);
        den.x += e0; den.y += e1; den.z += e2; den.w += e3;
        num.x = fmaf(e0, m.x * a, num.x);
        num.y = fmaf(e1, m.y * a, num.y);
        num.z = fmaf(e2, m.z * a, num.z);
        num.w = fmaf(e3, m.w * a, num.w);
    }
    if (rem) {
        bool v = e16 < rem;
        float vm = v ? 1.f : 0.f;
        int s = sp[v ? k : 0];
        float4 m = make_float4(0.f, 0.f, 0.f, 0.f);
        if (v) m = *(const float4*)(g_xl2 + s * 8 + q * 4);
        float p = sm_p[w][k];
        float a = p * rinv;
        float we = a * tl2e;
        float e0 = ex2f(m.x * we) * vm;
        float e1 = ex2f(m.y * we) * vm;
        float e2 = ex2f(m.z * we) * vm;
        float e3 = ex2f(m.w * we) * vm;
        den.x += e0; den.y += e1; den.z += e2; den.w += e3;
        num.x = fmaf(e0, m.x * a, num.x);
        num.y = fmaf(e1, m.y * a, num.y);
        num.z = fmaf(e2, m.z * a, num.z);
        num.w = fmaf(e3, m.w * a, num.w);
    }
    if (deg > CAP) {
        int ovfn = g_ovf_cnt2;
        for (int i = 0; i < ovfn; i++) {
            if (g_ovfd[i] == node) {
                float4 m = make_float4(0.f, 0.f, 0.f, 0.f);
                if (e16 == 0) m = *(const float4*)(g_xl2 + g_ovfs[i] * 8 + q * 4);
                float y0 = m.x + xr.x, y1 = m.y + xr.y, y2 = m.z + xr.z, y3 = m.w + xr.w;
                float sc = a06x * y0;
                sc = fmaf(a04x, fabsf(y0), sc);
                sc = fmaf(a06y, y1, sc); sc = fmaf(a04y, fabsf(y1), sc);
                sc = fmaf(a06z, y2, sc); sc = fmaf(a04z, fabsf(y2), sc);
                sc = fmaf(a06w, y3, sc); sc = fmaf(a04w, fabsf(y3), sc);
                sc += __shfl_xor_sync(0xffffffffu, sc, 1);
                if (e16 == 0) {
                    float p = ex2f(sc);
                    float a = p * rinv;
                    float we = a * tl2e;
                    float e0 = ex2f(m.x * we);
                    float e1 = ex2f(m.y * we);
                    float e2 = ex2f(m.z * we);
                    float e3 = ex2f(m.w * we);
                    den.x += e0; den.y += e1; den.z += e2; den.w += e3;
                    num.x = fmaf(e0, m.x * a, num.x);
                    num.y = fmaf(e1, m.y * a, num.y);
                    num.z = fmaf(e2, m.z * a, num.z);
                    num.w = fmaf(e3, m.w * a, num.w);
                }
            }
        }
    }
#pragma unroll
    for (int o = 2; o < 32; o <<= 1) {
        num.x += __shfl_xor_sync(0xffffffffu, num.x, o);
        num.y += __shfl_xor_sync(0xffffffffu, num.y, o);
        num.z += __shfl_xor_sync(0xffffffffu, num.z, o);
        num.w += __shfl_xor_sync(0xffffffffu, num.w, o);
        den.x += __shfl_xor_sync(0xffffffffu, den.x, o);
        den.y += __shfl_xor_sync(0xffffffffu, den.y, o);
        den.z += __shfl_xor_sync(0xffffffffu, den.z, o);
        den.w += __shfl_xor_sync(0xffffffffu, den.w, o);
    }

    // ---- fused head: lanes pair via q ----
    float4 b4v = *(const float4*)(bias + q * 4);
    float4 l4 = *(const float4*)(g_lin2 + node * 8 + q * 4);
    float hq[4];
    {
        float g0 = (den.x > 0.f) ? __fdividef(num.x, den.x) : 0.f;
        float g1 = (den.y > 0.f) ? __fdividef(num.y, den.y) : 0.f;
        float g2v = (den.z > 0.f) ? __fdividef(num.z, den.z) : 0.f;
        float g3 = (den.w > 0.f) ? __fdividef(num.w, den.w) : 0.f;
        hq[0] = fmaxf(g0 + b4v.x + l4.x, 0.f);
        hq[1] = fmaxf(g1 + b4v.y + l4.y, 0.f);
        hq[2] = fmaxf(g2v + b4v.z + l4.z, 0.f);
        hq[3] = fmaxf(g3 + b4v.w + l4.w, 0.f);
    }
    float part[8];
#pragma unroll
    for (int c = 0; c < 8; c++) {
        float acc = 0.f;
#pragma unroll
        for (int j = 0; j < 4; j++)
            acc = fmaf(hq[j], W3[(4 * q + j) * 8 + c], acc);
        part[c] = acc;
    }
#pragma unroll
    for (int c = 0; c < 8; c++)
        part[c] += __shfl_xor_sync(0xffffffffu, part[c], 1);
    if (lane == 0) {
        float s4 = b4[0];
#pragma unroll
        for (int c = 0; c < 8; c++) {
            float z = part[c] + b3[c];
            z = z > 0.f ? z : 0.f;
            s4 = fmaf(z, W4[c], s4);
        }
        s4 = s4 > 0.f ? s4 : 0.f;
        float s5 = W5[0] * s4 + b5[0];
        s5 = s5 > 0.f ? s5 : 0.f;
        float xo = Wout[0] * s5 + bout[0];
        float ls = (xo >= 0.f) ? -log1pf(expf(-xo)) : (xo - log1pf(expf(xo)));
        out[node] = ls;
    }
}

// ---------------- launch ----------------
extern "C" void kernel_launch(void* const* d_in, const int* in_sizes, int n_in,
                              void* d_out, int out_size)
{
    const float* x    = (const float*)d_in[0];
    const int*   ei   = (const int*)d_in[1];
    const int*   src  = ei;
    const int*   dst  = ei + EE;
    const float* Wl1  = (const float*)d_in[3];
    const float* Wr1  = (const float*)d_in[4];
    const float* att1 = (const float*)d_in[5];
    const float* b1   = (const float*)d_in[6];
    const float* Wlin1= (const float*)d_in[7];
    const float* blin1= (const float*)d_in[8];
    const float* Wl2  = (const float*)d_in[9];
    const float* Wr2  = (const float*)d_in[10];
    const float* att2 = (const float*)d_in[11];
    const float* b2   = (const float*)d_in[12];
    const float* Wlin2= (const float*)d_in[13];
    const float* blin2= (const float*)d_in[14];
    const float* t    = (const float*)d_in[15];
    const float* W3   = (const float*)d_in[16];
    const float* b3   = (const float*)d_in[17];
    const float* W4   = (const float*)d_in[18];
    const float* b4   = (const float*)d_in[19];
    const float* W5   = (const float*)d_in[20];
    const float* b5   = (const float*)d_in[21];
    const float* Wout = (const float*)d_in[22];
    const float* bout = (const float*)d_in[23];
    float* out = (float*)d_out;

    // 0: fused layer-1 GEMM + direct bucket scatter
    k_build<<<GEMM1_BLKS + HIST_BLKS, 256>>>(src, dst, x, Wl1, Wr1, Wlin1, blin1);
    // 1: edge layer 1 + fused layer-2 node GEMM epilogue
    k_edge1<<<(NN + 7) / 8, 256>>>(att1, b1, t, Wl2, Wr2, Wlin2, blin2);
    // 2: edge layer 2 + fused MLP head
    k_edge2h<<<(NN + 7) / 8, 256>>>(att2, b2, t, W3, b3, W4, b4, W5, b5, Wout, bout, out);
}

// round 9
// speedup vs baseline: 1.5127x; 1.3546x over previous
#include <cuda_runtime.h>

#define NN 100000
#define EE 3200000
#define FIN 128
#define CAP 128                // fixed bucket capacity per node
#define GEMM1_BLKS 782         // ceil(NN/128)
#define HIST_BLKS 1563         // ceil(EE/2048), 8 edges/thread
#define L2E 1.44269504f

// ---------------- scratch (static device globals; no allocs) ----------------
__device__ int   g_cnt[NN];          // zero at load; re-zeroed by k_edge2h
__device__ int   g_srcs[NN * CAP];   // fixed-capacity CSR buckets
__device__ int   g_ovf_cnt;          // overflow count (build writes, gemm2 swaps)
__device__ int   g_ovf_cnt2;         // snapshot for edge2h
__device__ int   g_ovfd[EE];         // overflow dst (cold)
__device__ int   g_ovfs[EE];         // overflow src (cold)
__device__ float g_xl1[NN * 16];
__device__ float g_xr1[NN * 16];
__device__ float g_lin1[NN * 16];
__device__ float g_h[NN * 16];
__device__ float g_xl2[NN * 8];
__device__ float g_xr2[NN * 8];
__device__ float g_lin2[NN * 8];

__device__ __forceinline__ float ex2f(float x) {
    float y; asm("ex2.approx.f32 %0, %1;" : "=f"(y) : "f"(x)); return y;
}

__device__ __forceinline__ void scatter_one(int d, int s) {
    int r = atomicAdd(&g_cnt[d], 1);
    if (r < CAP) {
        g_srcs[d * CAP + r] = s;
    } else {
        int o = atomicAdd(&g_ovf_cnt, 1);
        g_ovfd[o] = d;
        g_ovfs[o] = s;
    }
}

// ---- fused build: layer-1 GEMM (blocks 0..781) + bucket scatter (rest) -----
__global__ void __launch_bounds__(256) k_build(
    const int* __restrict__ src, const int* __restrict__ dst,
    const float* __restrict__ x, const float* __restrict__ Wl,
    const float* __restrict__ Wr, const float* __restrict__ Wlin,
    const float* __restrict__ blin)
{
    __shared__ float sx[128][36];
    __shared__ float sw[32][48];
    int t = threadIdx.x;
    int b = blockIdx.x;

    if (b >= GEMM1_BLKS) {
        // ---- scatter: 8 edges/thread, int4 loads, 8 atomics in flight ----
        int bb = b - GEMM1_BLKS;
        int e0 = bb * 2048 + t * 4;
        int e1 = e0 + 1024;
        bool v0 = e0 < EE, v1 = e1 < EE;   // EE % 1024 == 0: all-or-nothing
        int4 d0, s0, d1, s1;
        if (v0) { d0 = *(const int4*)(dst + e0); s0 = *(const int4*)(src + e0); }
        if (v1) { d1 = *(const int4*)(dst + e1); s1 = *(const int4*)(src + e1); }
        if (v0) {
            scatter_one(d0.x, s0.x);
            scatter_one(d0.y, s0.y);
            scatter_one(d0.z, s0.z);
            scatter_one(d0.w, s0.w);
        }
        if (v1) {
            scatter_one(d1.x, s1.x);
            scatter_one(d1.y, s1.y);
            scatter_one(d1.z, s1.z);
            scatter_one(d1.w, s1.w);
        }
        return;
    }

    // ---- gemm1: 128 rows x 48 cols; thread: 4 rows x 6 cols; K tile 32 ----
    int cg = t & 7, rg = t >> 3;
    int c0 = cg * 6;
    int rowbase = b * 128;
    float acc[4][6];
#pragma unroll
    for (int i = 0; i < 4; i++)
#pragma unroll
        for (int j = 0; j < 6; j++) acc[i][j] = 0.f;

    for (int kb = 0; kb < FIN; kb += 32) {
#pragma unroll
        for (int n = 0; n < 4; n++) {
            int idx = t + n * 256;
            int r = idx >> 3, k4 = idx & 7;
            int gr = rowbase + r;
            float4 val = make_float4(0.f, 0.f, 0.f, 0.f);
            if (gr < NN) val = *(const float4*)(x + gr * FIN + kb + k4 * 4);
            *(float4*)&sx[r][k4 * 4] = val;
        }
        for (int idx = t; idx < 32 * 48; idx += 256) {
            int k = idx / 48, j = idx % 48;
            int gk = kb + k;
            float val;
            if (j < 16)      val = Wl[gk * 16 + j];
            else if (j < 32) val = Wr[gk * 16 + j - 16];
            else             val = Wlin[gk * 16 + j - 32];
            sw[k][j] = val;
        }
        __syncthreads();
#pragma unroll
        for (int k = 0; k < 32; k += 4) {
            float xv[4][4];
#pragma unroll
            for (int i = 0; i < 4; i++) {
                float4 tmp = *(const float4*)&sx[rg * 4 + i][k];
                xv[i][0] = tmp.x; xv[i][1] = tmp.y; xv[i][2] = tmp.z; xv[i][3] = tmp.w;
            }
#pragma unroll
            for (int kk = 0; kk < 4; kk++) {
                float wv[6];
#pragma unroll
                for (int j = 0; j < 6; j++) wv[j] = sw[k + kk][c0 + j];
#pragma unroll
                for (int i = 0; i < 4; i++)
#pragma unroll
                    for (int j = 0; j < 6; j++)
                        acc[i][j] = fmaf(xv[i][kk], wv[j], acc[i][j]);
            }
        }
        __syncthreads();
    }
#pragma unroll
    for (int i = 0; i < 4; i++) {
        int gr = rowbase + rg * 4 + i;
        if (gr < NN) {
#pragma unroll
            for (int j = 0; j < 6; j++) {
                int c = c0 + j;
                if (c < 16)      g_xl1[gr * 16 + c] = acc[i][j];
                else if (c < 32) g_xr1[gr * 16 + (c - 16)] = acc[i][j];
                else             g_lin1[gr * 16 + (c - 32)] = acc[i][j] + blin[c - 32];
            }
        }
    }
}

// ---------------- edge kernel layer 1: warp/node, 4 lanes/edge --------------
__global__ void __launch_bounds__(256) k_edge1(
    const float* __restrict__ att, const float* __restrict__ bias,
    const float* __restrict__ tptr)
{
    __shared__ float sm_p[8][CAP];
    int w = threadIdx.x >> 5;
    int lane = threadIdx.x & 31;
    int node = blockIdx.x * 8 + w;
    if (node >= NN) return;
    int q = lane & 3, e8 = lane >> 2;
    int deg = g_cnt[node];
    int degf = deg < CAP ? deg : CAP;
    const int* sp = g_srcs + node * CAP;
    float tl2e = tptr[0] * L2E;
    float4 a4 = *(const float4*)(att + q * 4);
    float4 xr = *(const float4*)(g_xr1 + node * 16 + q * 4);
    float a06x = 0.6f * L2E * a4.x, a06y = 0.6f * L2E * a4.y;
    float a06z = 0.6f * L2E * a4.z, a06w = 0.6f * L2E * a4.w;
    float a04x = 0.4f * L2E * a4.x, a04y = 0.4f * L2E * a4.y;
    float a04z = 0.4f * L2E * a4.z, a04w = 0.4f * L2E * a4.w;
    int nfull = degf >> 3, rem = degf & 7;

    // ---- pass 1: scores -> p (cached in smem), accumulate S ----
    float S = 0.f;
    int k = e8;
#pragma unroll 2
    for (int it = 0; it < nfull; it++, k += 8) {
        int s = sp[k];
        float4 m = *(const float4*)(g_xl1 + s * 16 + q * 4);
        float y0 = m.x + xr.x, y1 = m.y + xr.y, y2 = m.z + xr.z, y3 = m.w + xr.w;
        float sc = a06x * y0;
        sc = fmaf(a04x, fabsf(y0), sc);
        sc = fmaf(a06y, y1, sc); sc = fmaf(a04y, fabsf(y1), sc);
        sc = fmaf(a06z, y2, sc); sc = fmaf(a04z, fabsf(y2), sc);
        sc = fmaf(a06w, y3, sc); sc = fmaf(a04w, fabsf(y3), sc);
        sc += __shfl_xor_sync(0xffffffffu, sc, 1);
        sc += __shfl_xor_sync(0xffffffffu, sc, 2);
        float p = ex2f(sc);
        if (q == 0) sm_p[w][k] = p;
        S += p;
    }
    if (rem) {
        bool v = e8 < rem;
        int s = sp[v ? k : 0];
        float4 m = make_float4(0.f, 0.f, 0.f, 0.f);
        if (v) m = *(const float4*)(g_xl1 + s * 16 + q * 4);
        float y0 = m.x + xr.x, y1 = m.y + xr.y, y2 = m.z + xr.z, y3 = m.w + xr.w;
        float sc = a06x * y0;
        sc = fmaf(a04x, fabsf(y0), sc);
        sc = fmaf(a06y, y1, sc); sc = fmaf(a04y, fabsf(y1), sc);
        sc = fmaf(a06z, y2, sc); sc = fmaf(a04z, fabsf(y2), sc);
        sc = fmaf(a06w, y3, sc); sc = fmaf(a04w, fabsf(y3), sc);
        sc += __shfl_xor_sync(0xffffffffu, sc, 1);
        sc += __shfl_xor_sync(0xffffffffu, sc, 2);
        float p = v ? ex2f(sc) : 0.f;
        if (q == 0) sm_p[w][k] = p;
        S += p;
    }
    // ---- pass 1: overflow list (cold) ----
    if (deg > CAP) {
        int ovfn = g_ovf_cnt;
        for (int i = 0; i < ovfn; i++) {
            if (g_ovfd[i] == node) {
                float4 m = make_float4(0.f, 0.f, 0.f, 0.f);
                if (e8 == 0) m = *(const float4*)(g_xl1 + g_ovfs[i] * 16 + q * 4);
                float y0 = m.x + xr.x, y1 = m.y + xr.y, y2 = m.z + xr.z, y3 = m.w + xr.w;
                float sc = a06x * y0;
                sc = fmaf(a04x, fabsf(y0), sc);
                sc = fmaf(a06y, y1, sc); sc = fmaf(a04y, fabsf(y1), sc);
                sc = fmaf(a06z, y2, sc); sc = fmaf(a04z, fabsf(y2), sc);
                sc = fmaf(a06w, y3, sc); sc = fmaf(a04w, fabsf(y3), sc);
                sc += __shfl_xor_sync(0xffffffffu, sc, 1);
                sc += __shfl_xor_sync(0xffffffffu, sc, 2);
                if (e8 == 0) S += ex2f(sc);
            }
        }
    }
#pragma unroll
    for (int o = 16; o; o >>= 1) S += __shfl_xor_sync(0xffffffffu, S, o);
    float rinv = __fdividef(4.f, S);   // S counted 4x per edge
    __syncwarp();

    // ---- pass 2: re-gather (L1-hot) + fused softmax-agg num/den ----
    float4 num = make_float4(0.f, 0.f, 0.f, 0.f);
    float4 den = make_float4(0.f, 0.f, 0.f, 0.f);
    k = e8;
#pragma unroll 2
    for (int it = 0; it < nfull; it++, k += 8) {
        int s = sp[k];
        float4 m = *(const float4*)(g_xl1 + s * 16 + q * 4);
        float p = sm_p[w][k];
        float a = p * rinv;
        float we = a * tl2e;
        float e0 = ex2f(m.x * we);
        float e1 = ex2f(m.y * we);
        float e2 = ex2f(m.z * we);
        float e3 = ex2f(m.w * we);
        den.x += e0; den.y += e1; den.z += e2; den.w += e3;
        num.x = fmaf(e0, m.x * a, num.x);
        num.y = fmaf(e1, m.y * a, num.y);
        num.z = fmaf(e2, m.z * a, num.z);
        num.w = fmaf(e3, m.w * a, num.w);
    }
    if (rem) {
        bool v = e8 < rem;
        float vm = v ? 1.f : 0.f;
        int s = sp[v ? k : 0];
        float4 m = make_float4(0.f, 0.f, 0.f, 0.f);
        if (v) m = *(const float4*)(g_xl1 + s * 16 + q * 4);
        float p = sm_p[w][k];
        float a = p * rinv;
        float we = a * tl2e;
        float e0 = ex2f(m.x * we) * vm;
        float e1 = ex2f(m.y * we) * vm;
        float e2 = ex2f(m.z * we) * vm;
        float e3 = ex2f(m.w * we) * vm;
        den.x += e0; den.y += e1; den.z += e2; den.w += e3;
        num.x = fmaf(e0, m.x * a, num.x);
        num.y = fmaf(e1, m.y * a, num.y);
        num.z = fmaf(e2, m.z * a, num.z);
        num.w = fmaf(e3, m.w * a, num.w);
    }
    // ---- pass 2: overflow list (cold) ----
    if (deg > CAP) {
        int ovfn = g_ovf_cnt;
        for (int i = 0; i < ovfn; i++) {
            if (g_ovfd[i] == node) {
                float4 m = make_float4(0.f, 0.f, 0.f, 0.f);
                if (e8 == 0) m = *(const float4*)(g_xl1 + g_ovfs[i] * 16 + q * 4);
                float y0 = m.x + xr.x, y1 = m.y + xr.y, y2 = m.z + xr.z, y3 = m.w + xr.w;
                float sc = a06x * y0;
                sc = fmaf(a04x, fabsf(y0), sc);
                sc = fmaf(a06y, y1, sc); sc = fmaf(a04y, fabsf(y1), sc);
                sc = fmaf(a06z, y2, sc); sc = fmaf(a04z, fabsf(y2), sc);
                sc = fmaf(a06w, y3, sc); sc = fmaf(a04w, fabsf(y3), sc);
                sc += __shfl_xor_sync(0xffffffffu, sc, 1);
                sc += __shfl_xor_sync(0xffffffffu, sc, 2);
                if (e8 == 0) {
                    float p = ex2f(sc);
                    float a = p * rinv;
                    float we = a * tl2e;
                    float e0 = ex2f(m.x * we);
                    float e1 = ex2f(m.y * we);
                    float e2 = ex2f(m.z * we);
                    float e3 = ex2f(m.w * we);
                    den.x += e0; den.y += e1; den.z += e2; den.w += e3;
                    num.x = fmaf(e0, m.x * a, num.x);
                    num.y = fmaf(e1, m.y * a, num.y);
                    num.z = fmaf(e2, m.z * a, num.z);
                    num.w = fmaf(e3, m.w * a, num.w);
                }
            }
        }
    }
#pragma unroll
    for (int o = 4; o < 32; o <<= 1) {
        num.x += __shfl_xor_sync(0xffffffffu, num.x, o);
        num.y += __shfl_xor_sync(0xffffffffu, num.y, o);
        num.z += __shfl_xor_sync(0xffffffffu, num.z, o);
        num.w += __shfl_xor_sync(0xffffffffu, num.w, o);
        den.x += __shfl_xor_sync(0xffffffffu, den.x, o);
        den.y += __shfl_xor_sync(0xffffffffu, den.y, o);
        den.z += __shfl_xor_sync(0xffffffffu, den.z, o);
        den.w += __shfl_xor_sync(0xffffffffu, den.w, o);
    }
    if (e8 == 0) {
        float4 b4 = *(const float4*)(bias + q * 4);
        float4 l4 = *(const float4*)(g_lin1 + node * 16 + q * 4);
        float4 o4;
        float g0 = (den.x > 0.f) ? __fdividef(num.x, den.x) : 0.f;
        float g1 = (den.y > 0.f) ? __fdividef(num.y, den.y) : 0.f;
        float g2v = (den.z > 0.f) ? __fdividef(num.z, den.z) : 0.f;
        float g3 = (den.w > 0.f) ? __fdividef(num.w, den.w) : 0.f;
        o4.x = fmaxf(g0 + b4.x + l4.x, 0.f);
        o4.y = fmaxf(g1 + b4.y + l4.y, 0.f);
        o4.z = fmaxf(g2v + b4.z + l4.z, 0.f);
        o4.w = fmaxf(g3 + b4.w + l4.w, 0.f);
        *(float4*)(g_h + node * 16 + q * 4) = o4;
    }
}

// ---------------- layer-2 node GEMM (+ overflow counter hand-off) -----------
__global__ void __launch_bounds__(256) k_gemm2(
    const float* __restrict__ Wl, const float* __restrict__ Wr,
    const float* __restrict__ Wlin, const float* __restrict__ blin)
{
    if (blockIdx.x == 0 && threadIdx.x == 0) {
        g_ovf_cnt2 = g_ovf_cnt;
        g_ovf_cnt = 0;
    }
    __shared__ float sw[16 * 24];
    int t = threadIdx.x;
    for (int idx = t; idx < 16 * 24; idx += 256) {
        int k = idx / 24, j = idx % 24;
        float v;
        if (j < 8)       v = Wl[k * 8 + j];
        else if (j < 16) v = Wr[k * 8 + j - 8];
        else             v = Wlin[k * 8 + j - 16];
        sw[idx] = v;
    }
    __syncthreads();
    int i = blockIdx.x * blockDim.x + t;
    if (i >= NN) return;
    const float4* hp = (const float4*)(g_h + i * 16);
    float4 q0 = hp[0], q1 = hp[1], q2 = hp[2], q3 = hp[3];
    float h[16] = {q0.x, q0.y, q0.z, q0.w, q1.x, q1.y, q1.z, q1.w,
                   q2.x, q2.y, q2.z, q2.w, q3.x, q3.y, q3.z, q3.w};
    float acc[24];
#pragma unroll
    for (int j = 0; j < 24; j++) acc[j] = 0.f;
#pragma unroll
    for (int k = 0; k < 16; k++) {
        float hv = h[k];
#pragma unroll
        for (int j = 0; j < 24; j++) acc[j] = fmaf(hv, sw[k * 24 + j], acc[j]);
    }
#pragma unroll
    for (int j = 0; j < 8; j++) {
        g_xl2[i * 8 + j] = acc[j];
        g_xr2[i * 8 + j] = acc[8 + j];
        g_lin2[i * 8 + j] = acc[16 + j] + blin[j];
    }
}

// ------- edge kernel layer 2 (2 lanes/edge) + fused MLP head + log_sigmoid --
__global__ void __launch_bounds__(256) k_edge2h(
    const float* __restrict__ att, const float* __restrict__ bias,
    const float* __restrict__ tptr,
    const float* __restrict__ W3, const float* __restrict__ b3,
    const float* __restrict__ W4, const float* __restrict__ b4,
    const float* __restrict__ W5, const float* __restrict__ b5,
    const float* __restrict__ Wout, const float* __restrict__ bout,
    float* __restrict__ out)
{
    __shared__ float sm_p[8][CAP];
    int w = threadIdx.x >> 5;
    int lane = threadIdx.x & 31;
    int node = blockIdx.x * 8 + w;
    if (node >= NN) return;
    int q = lane & 1, e16 = lane >> 1;
    int deg = g_cnt[node];
    if (lane == 0) g_cnt[node] = 0;   // reset for next launch
    int degf = deg < CAP ? deg : CAP;
    const int* sp = g_srcs + node * CAP;
    float tl2e = tptr[0] * L2E;
    float4 a4 = *(const float4*)(att + q * 4);
    float4 xr = *(const float4*)(g_xr2 + node * 8 + q * 4);
    float a06x = 0.6f * L2E * a4.x, a06y = 0.6f * L2E * a4.y;
    float a06z = 0.6f * L2E * a4.z, a06w = 0.6f * L2E * a4.w;
    float a04x = 0.4f * L2E * a4.x, a04y = 0.4f * L2E * a4.y;
    float a04z = 0.4f * L2E * a4.z, a04w = 0.4f * L2E * a4.w;
    int nfull = degf >> 4, rem = degf & 15;

    float S = 0.f;
    int k = e16;
#pragma unroll 2
    for (int it = 0; it < nfull; it++, k += 16) {
        int s = sp[k];
        float4 m = *(const float4*)(g_xl2 + s * 8 + q * 4);
        float y0 = m.x + xr.x, y1 = m.y + xr.y, y2 = m.z + xr.z, y3 = m.w + xr.w;
        float sc = a06x * y0;
        sc = fmaf(a04x, fabsf(y0), sc);
        sc = fmaf(a06y, y1, sc); sc = fmaf(a04y, fabsf(y1), sc);
        sc = fmaf(a06z, y2, sc); sc = fmaf(a04z, fabsf(y2), sc);
        sc = fmaf(a06w, y3, sc); sc = fmaf(a04w, fabsf(y3), sc);
        sc += __shfl_xor_sync(0xffffffffu, sc, 1);
        float p = ex2f(sc);
        if (q == 0) sm_p[w][k] = p;
        S += p;
    }
    if (rem) {
        bool v = e16 < rem;
        int s = sp[v ? k : 0];
        float4 m = make_float4(0.f, 0.f, 0.f, 0.f);
        if (v) m = *(const float4*)(g_xl2 + s * 8 + q * 4);
        float y0 = m.x + xr.x, y1 = m.y + xr.y, y2 = m.z + xr.z, y3 = m.w + xr.w;
        float sc = a06x * y0;
        sc = fmaf(a04x, fabsf(y0), sc);
        sc = fmaf(a06y, y1, sc); sc = fmaf(a04y, fabsf(y1), sc);
        sc = fmaf(a06z, y2, sc); sc = fmaf(a04z, fabsf(y2), sc);
        sc = fmaf(a06w, y3, sc); sc = fmaf(a04w, fabsf(y3), sc);
        sc += __shfl_xor_sync(0xffffffffu, sc, 1);
        float p = v ? ex2f(sc) : 0.f;
        if (q == 0) sm_p[w][k] = p;
        S += p;
    }
    if (deg > CAP) {
        int ovfn = g_ovf_cnt2;
        for (int i = 0; i < ovfn; i++) {
            if (g_ovfd[i] == node) {
                float4 m = make_float4(0.f, 0.f, 0.f, 0.f);
                if (e16 == 0) m = *(const float4*)(g_xl2 + g_ovfs[i] * 8 + q * 4);
                float y0 = m.x + xr.x, y1 = m.y + xr.y, y2 = m.z + xr.z, y3 = m.w + xr.w;
                float sc = a06x * y0;
                sc = fmaf(a04x, fabsf(y0), sc);
                sc = fmaf(a06y, y1, sc); sc = fmaf(a04y, fabsf(y1), sc);
                sc = fmaf(a06z, y2, sc); sc = fmaf(a04z, fabsf(y2), sc);
                sc = fmaf(a06w, y3, sc); sc = fmaf(a04w, fabsf(y3), sc);
                sc += __shfl_xor_sync(0xffffffffu, sc, 1);
                if (e16 == 0) S += ex2f(sc);
            }
        }
    }
#pragma unroll
    for (int o = 16; o; o >>= 1) S += __shfl_xor_sync(0xffffffffu, S, o);
    float rinv = __fdividef(2.f, S);   // S counted 2x per edge
    __syncwarp();

    float4 num = make_float4(0.f, 0.f, 0.f, 0.f);
    float4 den = make_float4(0.f, 0.f, 0.f, 0.f);
    k = e16;
#pragma unroll 2
    for (int it = 0; it < nfull; it++, k += 16) {
        int s = sp[k];
        float4 m = *(const float4*)(g_xl2 + s * 8 + q * 4);
        float p = sm_p[w][k];
        float a = p * rinv;
        float we = a * tl2e;
        float e0 = ex2f(m.x * we);
        float e1 = ex2f(m.y * we);
        float e2 = ex2f(m.z * we);
        float e3 = ex2f(m.w * we);
        den.x += e0; den.y += e1; den.z += e2; den.w += e3;
        num.x = fmaf(e0, m.x * a, num.x);
        num.y = fmaf(e1, m.y * a, num.y);
        num.z = fmaf(e2, m.z * a, num.z);
        num.w = fmaf(e3, m.w * a, num.w);
    }
    if (rem) {
        bool v = e16 < rem;
        float vm = v ? 1.f : 0.f;
        int s = sp[v ? k : 0];
        float4 m = make_float4(0.f, 0.f, 0.f, 0.f);
        if (v) m = *(const float4*)(g_xl2 + s * 8 + q * 4);
        float p = sm_p[w][k];
        float a = p * rinv;
        float we = a * tl2e;
        float e0 = ex2f(m.x * we) * vm;
        float e1 = ex2f(m.y * we) * vm;
        float e2 = ex2f(m.z * we) * vm;
        float e3 = ex2f(m.w * we) * vm;
        den.x += e0; den.y += e1; den.z += e2; den.w += e3;
        num.x = fmaf(e0, m.x * a, num.x);
        num.y = fmaf(e1, m.y * a, num.y);
        num.z = fmaf(e2, m.z * a, num.z);
        num.w = fmaf(e3, m.w * a, num.w);
    }
    if (deg > CAP) {
        int ovfn = g_ovf_cnt2;
        for (int i = 0; i < ovfn; i++) {
            if (g_ovfd[i] == node) {
                float4 m = make_float4(0.f, 0.f, 0.f, 0.f);
                if (e16 == 0) m = *(const float4*)(g_xl2 + g_ovfs[i] * 8 + q * 4);
                float y0 = m.x + xr.x, y1 = m.y + xr.y, y2 = m.z + xr.z, y3 = m.w + xr.w;
                float sc = a06x * y0;
                sc = fmaf(a04x, fabsf(y0), sc);
                sc = fmaf(a06y, y1, sc); sc = fmaf(a04y, fabsf(y1), sc);
                sc = fmaf(a06z, y2, sc); sc = fmaf(a04z, fabsf(y2), sc);
                sc = fmaf(a06w, y3, sc); sc = fmaf(a04w, fabsf(y3), sc);
                sc += __shfl_xor_sync(0xffffffffu, sc, 1);
                if (e16 == 0) {
                    float p = ex2f(sc);
                    float a = p * rinv;
                    float we = a * tl2e;
                    float e0 = ex2f(m.x * we);
                    float e1 = ex2f(m.y * we);
                    float e2 = ex2f(m.z * we);
                    float e3 = ex2f(m.w * we);
                    den.x += e0; den.y += e1; den.z += e2; den.w += e3;
                    num.x = fmaf(e0, m.x * a, num.x);
                    num.y = fmaf(e1, m.y * a, num.y);
                    num.z = fmaf(e2, m.z * a, num.z);
                    num.w = fmaf(e3, m.w * a, num.w);
                }
            }
        }
    }
#pragma unroll
    for (int o = 2; o < 32; o <<= 1) {
        num.x += __shfl_xor_sync(0xffffffffu, num.x, o);
        num.y += __shfl_xor_sync(0xffffffffu, num.y, o);
        num.z += __shfl_xor_sync(0xffffffffu, num.z, o);
        num.w += __shfl_xor_sync(0xffffffffu, num.w, o);
        den.x += __shfl_xor_sync(0xffffffffu, den.x, o);
        den.y += __shfl_xor_sync(0xffffffffu, den.y, o);
        den.z += __shfl_xor_sync(0xffffffffu, den.z, o);
        den.w += __shfl_xor_sync(0xffffffffu, den.w, o);
    }

    // ---- fused head: lanes pair via q ----
    float4 b4v = *(const float4*)(bias + q * 4);
    float4 l4 = *(const float4*)(g_lin2 + node * 8 + q * 4);
    float hq[4];
    {
        float g0 = (den.x > 0.f) ? __fdividef(num.x, den.x) : 0.f;
        float g1 = (den.y > 0.f) ? __fdividef(num.y, den.y) : 0.f;
        float g2v = (den.z > 0.f) ? __fdividef(num.z, den.z) : 0.f;
        float g3 = (den.w > 0.f) ? __fdividef(num.w, den.w) : 0.f;
        hq[0] = fmaxf(g0 + b4v.x + l4.x, 0.f);
        hq[1] = fmaxf(g1 + b4v.y + l4.y, 0.f);
        hq[2] = fmaxf(g2v + b4v.z + l4.z, 0.f);
        hq[3] = fmaxf(g3 + b4v.w + l4.w, 0.f);
    }
    float part[8];
#pragma unroll
    for (int c = 0; c < 8; c++) {
        float acc = 0.f;
#pragma unroll
        for (int j = 0; j < 4; j++)
            acc = fmaf(hq[j], W3[(4 * q + j) * 8 + c], acc);
        part[c] = acc;
    }
#pragma unroll
    for (int c = 0; c < 8; c++)
        part[c] += __shfl_xor_sync(0xffffffffu, part[c], 1);
    if (lane == 0) {
        float s4 = b4[0];
#pragma unroll
        for (int c = 0; c < 8; c++) {
            float z = part[c] + b3[c];
            z = z > 0.f ? z : 0.f;
            s4 = fmaf(z, W4[c], s4);
        }
        s4 = s4 > 0.f ? s4 : 0.f;
        float s5 = W5[0] * s4 + b5[0];
        s5 = s5 > 0.f ? s5 : 0.f;
        float xo = Wout[0] * s5 + bout[0];
        float ls = (xo >= 0.f) ? -log1pf(expf(-xo)) : (xo - log1pf(expf(xo)));
        out[node] = ls;
    }
}

// ---------------- launch ----------------
extern "C" void kernel_launch(void* const* d_in, const int* in_sizes, int n_in,
                              void* d_out, int out_size)
{
    const float* x    = (const float*)d_in[0];
    const int*   ei   = (const int*)d_in[1];
    const int*   src  = ei;
    const int*   dst  = ei + EE;
    const float* Wl1  = (const float*)d_in[3];
    const float* Wr1  = (const float*)d_in[4];
    const float* att1 = (const float*)d_in[5];
    const float* b1   = (const float*)d_in[6];
    const float* Wlin1= (const float*)d_in[7];
    const float* blin1= (const float*)d_in[8];
    const float* Wl2  = (const float*)d_in[9];
    const float* Wr2  = (const float*)d_in[10];
    const float* att2 = (const float*)d_in[11];
    const float* b2   = (const float*)d_in[12];
    const float* Wlin2= (const float*)d_in[13];
    const float* blin2= (const float*)d_in[14];
    const float* t    = (const float*)d_in[15];
    const float* W3   = (const float*)d_in[16];
    const float* b3   = (const float*)d_in[17];
    const float* W4   = (const float*)d_in[18];
    const float* b4   = (const float*)d_in[19];
    const float* W5   = (const float*)d_in[20];
    const float* b5   = (const float*)d_in[21];
    const float* Wout = (const float*)d_in[22];
    const float* bout = (const float*)d_in[23];
    float* out = (float*)d_out;

    // 0: fused layer-1 GEMM + MLP-8 bucket scatter
    k_build<<<GEMM1_BLKS + HIST_BLKS, 256>>>(src, dst, x, Wl1, Wr1, Wlin1, blin1);
    // 1: edge layer 1
    k_edge1<<<(NN + 7) / 8, 256>>>(att1, b1, t);
    // 2: layer-2 GEMM (pool is identity) + overflow counter hand-off
    k_gemm2<<<(NN + 255) / 256, 256>>>(Wl2, Wr2, Wlin2, blin2);
    // 3: edge layer 2 + fused MLP head
    k_edge2h<<<(NN + 7) / 8, 256>>>(att2, b2, t, W3, b3, W4, b4, W5, b5, Wout, bout, out);
}

// round 10
// speedup vs baseline: 1.5240x; 1.0075x over previous
#include <cuda_runtime.h>

#define NN 100000
#define EE 3200000
#define FIN 128
#define CAP 128                // fixed bucket capacity per node
#define GEMM1_BLKS 782         // ceil(NN/128)
#define HIST_BLKS 1563         // ceil(EE/2048), 8 edges/thread
#define L2E 1.44269504f

// ---------------- scratch (static device globals; no allocs) ----------------
__device__ int   g_cnt[NN];          // zero at load; re-zeroed by k_edge2h
__device__ int   g_srcs[NN * CAP];   // fixed-capacity CSR buckets
__device__ int   g_ovf_cnt;          // overflow count (build writes, gemm2 swaps)
__device__ int   g_ovf_cnt2;         // snapshot for edge2h
__device__ int   g_ovfd[EE];         // overflow dst (cold)
__device__ int   g_ovfs[EE];         // overflow src (cold)
__device__ float g_xl1[NN * 16];
__device__ float g_xr1[NN * 16];
__device__ float g_lin1[NN * 16];
__device__ float g_h[NN * 16];
__device__ float g_xl2[NN * 8];
__device__ float g_xr2[NN * 8];
__device__ float g_lin2[NN * 8];

__device__ __forceinline__ float ex2f(float x) {
    float y; asm("ex2.approx.f32 %0, %1;" : "=f"(y) : "f"(x)); return y;
}

__device__ __forceinline__ void scatter_one(int d, int s) {
    int r = atomicAdd(&g_cnt[d], 1);
    if (r < CAP) {
        g_srcs[d * CAP + r] = s;
    } else {
        int o = atomicAdd(&g_ovf_cnt, 1);
        g_ovfd[o] = d;
        g_ovfs[o] = s;
    }
}

// ---- fused build: layer-1 GEMM (blocks 0..781) + bucket scatter (rest) -----
__global__ void __launch_bounds__(256) k_build(
    const int* __restrict__ src, const int* __restrict__ dst,
    const float* __restrict__ x, const float* __restrict__ Wl,
    const float* __restrict__ Wr, const float* __restrict__ Wlin,
    const float* __restrict__ blin)
{
    __shared__ float sx[128][36];
    __shared__ float sw[32][48];
    int t = threadIdx.x;
    int b = blockIdx.x;

    if (b >= GEMM1_BLKS) {
        // ---- scatter: 8 edges/thread, int4 loads, 8 atomics in flight ----
        int bb = b - GEMM1_BLKS;
        int e0 = bb * 2048 + t * 4;
        int e1 = e0 + 1024;
        bool v0 = e0 < EE, v1 = e1 < EE;   // EE % 1024 == 0: all-or-nothing
        int4 d0, s0, d1, s1;
        if (v0) { d0 = *(const int4*)(dst + e0); s0 = *(const int4*)(src + e0); }
        if (v1) { d1 = *(const int4*)(dst + e1); s1 = *(const int4*)(src + e1); }
        if (v0) {
            scatter_one(d0.x, s0.x);
            scatter_one(d0.y, s0.y);
            scatter_one(d0.z, s0.z);
            scatter_one(d0.w, s0.w);
        }
        if (v1) {
            scatter_one(d1.x, s1.x);
            scatter_one(d1.y, s1.y);
            scatter_one(d1.z, s1.z);
            scatter_one(d1.w, s1.w);
        }
        return;
    }

    // ---- gemm1: 128 rows x 48 cols; thread: 4 rows x 6 cols; K tile 32 ----
    int cg = t & 7, rg = t >> 3;
    int c0 = cg * 6;
    int rowbase = b * 128;
    float acc[4][6];
#pragma unroll
    for (int i = 0; i < 4; i++)
#pragma unroll
        for (int j = 0; j < 6; j++) acc[i][j] = 0.f;

    for (int kb = 0; kb < FIN; kb += 32) {
#pragma unroll
        for (int n = 0; n < 4; n++) {
            int idx = t + n * 256;
            int r = idx >> 3, k4 = idx & 7;
            int gr = rowbase + r;
            float4 val = make_float4(0.f, 0.f, 0.f, 0.f);
            if (gr < NN) val = *(const float4*)(x + gr * FIN + kb + k4 * 4);
            *(float4*)&sx[r][k4 * 4] = val;
        }
        for (int idx = t; idx < 32 * 48; idx += 256) {
            int k = idx / 48, j = idx % 48;
            int gk = kb + k;
            float val;
            if (j < 16)      val = Wl[gk * 16 + j];
            else if (j < 32) val = Wr[gk * 16 + j - 16];
            else             val = Wlin[gk * 16 + j - 32];
            sw[k][j] = val;
        }
        __syncthreads();
#pragma unroll
        for (int k = 0; k < 32; k += 4) {
            float xv[4][4];
#pragma unroll
            for (int i = 0; i < 4; i++) {
                float4 tmp = *(const float4*)&sx[rg * 4 + i][k];
                xv[i][0] = tmp.x; xv[i][1] = tmp.y; xv[i][2] = tmp.z; xv[i][3] = tmp.w;
            }
#pragma unroll
            for (int kk = 0; kk < 4; kk++) {
                float wv[6];
#pragma unroll
                for (int j = 0; j < 6; j++) wv[j] = sw[k + kk][c0 + j];
#pragma unroll
                for (int i = 0; i < 4; i++)
#pragma unroll
                    for (int j = 0; j < 6; j++)
                        acc[i][j] = fmaf(xv[i][kk], wv[j], acc[i][j]);
            }
        }
        __syncthreads();
    }
#pragma unroll
    for (int i = 0; i < 4; i++) {
        int gr = rowbase + rg * 4 + i;
        if (gr < NN) {
#pragma unroll
            for (int j = 0; j < 6; j++) {
                int c = c0 + j;
                if (c < 16)      g_xl1[gr * 16 + c] = acc[i][j];
                else if (c < 32) g_xr1[gr * 16 + (c - 16)] = acc[i][j];
                else             g_lin1[gr * 16 + (c - 32)] = acc[i][j] + blin[c - 32];
            }
        }
    }
}

// ---------------- edge kernel layer 1: warp/node, 4 lanes/edge --------------
__global__ void __launch_bounds__(256) k_edge1(
    const float* __restrict__ att, const float* __restrict__ bias,
    const float* __restrict__ tptr)
{
    __shared__ float sm_p[8][CAP];
    int w = threadIdx.x >> 5;
    int lane = threadIdx.x & 31;
    int node = blockIdx.x * 8 + w;
    if (node >= NN) return;
    int q = lane & 3, e8 = lane >> 2;
    int deg = g_cnt[node];
    int degf = deg < CAP ? deg : CAP;
    const int* sp = g_srcs + node * CAP;
    float tl2e = tptr[0] * L2E;
    float4 a4 = *(const float4*)(att + q * 4);
    float4 xr = *(const float4*)(g_xr1 + node * 16 + q * 4);
    float a06x = 0.6f * L2E * a4.x, a06y = 0.6f * L2E * a4.y;
    float a06z = 0.6f * L2E * a4.z, a06w = 0.6f * L2E * a4.w;
    float a04x = 0.4f * L2E * a4.x, a04y = 0.4f * L2E * a4.y;
    float a04z = 0.4f * L2E * a4.z, a04w = 0.4f * L2E * a4.w;
    int nfull = degf >> 3, rem = degf & 7;

    // ---- pass 1: scores -> p (cached in smem), accumulate S ----
    float S = 0.f;
    int k = e8;
#pragma unroll 2
    for (int it = 0; it < nfull; it++, k += 8) {
        int s = sp[k];
        float4 m = *(const float4*)(g_xl1 + s * 16 + q * 4);
        float y0 = m.x + xr.x, y1 = m.y + xr.y, y2 = m.z + xr.z, y3 = m.w + xr.w;
        float sc = a06x * y0;
        sc = fmaf(a04x, fabsf(y0), sc);
        sc = fmaf(a06y, y1, sc); sc = fmaf(a04y, fabsf(y1), sc);
        sc = fmaf(a06z, y2, sc); sc = fmaf(a04z, fabsf(y2), sc);
        sc = fmaf(a06w, y3, sc); sc = fmaf(a04w, fabsf(y3), sc);
        sc += __shfl_xor_sync(0xffffffffu, sc, 1);
        sc += __shfl_xor_sync(0xffffffffu, sc, 2);
        float p = ex2f(sc);
        if (q == 0) sm_p[w][k] = p;
        S += p;
    }
    if (rem) {
        bool v = e8 < rem;
        int s = sp[v ? k : 0];
        float4 m = make_float4(0.f, 0.f, 0.f, 0.f);
        if (v) m = *(const float4*)(g_xl1 + s * 16 + q * 4);
        float y0 = m.x + xr.x, y1 = m.y + xr.y, y2 = m.z + xr.z, y3 = m.w + xr.w;
        float sc = a06x * y0;
        sc = fmaf(a04x, fabsf(y0), sc);
        sc = fmaf(a06y, y1, sc); sc = fmaf(a04y, fabsf(y1), sc);
        sc = fmaf(a06z, y2, sc); sc = fmaf(a04z, fabsf(y2), sc);
        sc = fmaf(a06w, y3, sc); sc = fmaf(a04w, fabsf(y3), sc);
        sc += __shfl_xor_sync(0xffffffffu, sc, 1);
        sc += __shfl_xor_sync(0xffffffffu, sc, 2);
        float p = v ? ex2f(sc) : 0.f;
        if (q == 0) sm_p[w][k] = p;
        S += p;
    }
    // ---- pass 1: overflow list (cold) ----
    if (deg > CAP) {
        int ovfn = g_ovf_cnt;
        for (int i = 0; i < ovfn; i++) {
            if (g_ovfd[i] == node) {
                float4 m = make_float4(0.f, 0.f, 0.f, 0.f);
                if (e8 == 0) m = *(const float4*)(g_xl1 + g_ovfs[i] * 16 + q * 4);
                float y0 = m.x + xr.x, y1 = m.y + xr.y, y2 = m.z + xr.z, y3 = m.w + xr.w;
                float sc = a06x * y0;
                sc = fmaf(a04x, fabsf(y0), sc);
                sc = fmaf(a06y, y1, sc); sc = fmaf(a04y, fabsf(y1), sc);
                sc = fmaf(a06z, y2, sc); sc = fmaf(a04z, fabsf(y2), sc);
                sc = fmaf(a06w, y3, sc); sc = fmaf(a04w, fabsf(y3), sc);
                sc += __shfl_xor_sync(0xffffffffu, sc, 1);
                sc += __shfl_xor_sync(0xffffffffu, sc, 2);
                if (e8 == 0) S += ex2f(sc);
            }
        }
    }
#pragma unroll
    for (int o = 16; o; o >>= 1) S += __shfl_xor_sync(0xffffffffu, S, o);
    float rinv = __fdividef(4.f, S);   // S counted 4x per edge
    __syncwarp();

    // ---- pass 2: re-gather (L1-hot) + fused softmax-agg num/den ----
    float4 num = make_float4(0.f, 0.f, 0.f, 0.f);
    float4 den = make_float4(0.f, 0.f, 0.f, 0.f);
    k = e8;
#pragma unroll 2
    for (int it = 0; it < nfull; it++, k += 8) {
        int s = sp[k];
        float4 m = *(const float4*)(g_xl1 + s * 16 + q * 4);
        float p = sm_p[w][k];
        float a = p * rinv;
        float we = a * tl2e;
        float e0 = ex2f(m.x * we);
        float e1 = ex2f(m.y * we);
        float e2 = ex2f(m.z * we);
        float e3 = ex2f(m.w * we);
        den.x += e0; den.y += e1; den.z += e2; den.w += e3;
        num.x = fmaf(e0, m.x * a, num.x);
        num.y = fmaf(e1, m.y * a, num.y);
        num.z = fmaf(e2, m.z * a, num.z);
        num.w = fmaf(e3, m.w * a, num.w);
    }
    if (rem) {
        bool v = e8 < rem;
        float vm = v ? 1.f : 0.f;
        int s = sp[v ? k : 0];
        float4 m = make_float4(0.f, 0.f, 0.f, 0.f);
        if (v) m = *(const float4*)(g_xl1 + s * 16 + q * 4);
        float p = sm_p[w][k];
        float a = p * rinv;
        float we = a * tl2e;
        float e0 = ex2f(m.x * we) * vm;
        float e1 = ex2f(m.y * we) * vm;
        float e2 = ex2f(m.z * we) * vm;
        float e3 = ex2f(m.w * we) * vm;
        den.x += e0; den.y += e1; den.z += e2; den.w += e3;
        num.x = fmaf(e0, m.x * a, num.x);
        num.y = fmaf(e1, m.y * a, num.y);
        num.z = fmaf(e2, m.z * a, num.z);
        num.w = fmaf(e3, m.w * a, num.w);
    }
    // ---- pass 2: overflow list (cold) ----
    if (deg > CAP) {
        int ovfn = g_ovf_cnt;
        for (int i = 0; i < ovfn; i++) {
            if (g_ovfd[i] == node) {
                float4 m = make_float4(0.f, 0.f, 0.f, 0.f);
                if (e8 == 0) m = *(const float4*)(g_xl1 + g_ovfs[i] * 16 + q * 4);
                float y0 = m.x + xr.x, y1 = m.y + xr.y, y2 = m.z + xr.z, y3 = m.w + xr.w;
                float sc = a06x * y0;
                sc = fmaf(a04x, fabsf(y0), sc);
                sc = fmaf(a06y, y1, sc); sc = fmaf(a04y, fabsf(y1), sc);
                sc = fmaf(a06z, y2, sc); sc = fmaf(a04z, fabsf(y2), sc);
                sc = fmaf(a06w, y3, sc); sc = fmaf(a04w, fabsf(y3), sc);
                sc += __shfl_xor_sync(0xffffffffu, sc, 1);
                sc += __shfl_xor_sync(0xffffffffu, sc, 2);
                if (e8 == 0) {
                    float p = ex2f(sc);
                    float a = p * rinv;
                    float we = a * tl2e;
                    float e0 = ex2f(m.x * we);
                    float e1 = ex2f(m.y * we);
                    float e2 = ex2f(m.z * we);
                    float e3 = ex2f(m.w * we);
                    den.x += e0; den.y += e1; den.z += e2; den.w += e3;
                    num.x = fmaf(e0, m.x * a, num.x);
                    num.y = fmaf(e1, m.y * a, num.y);
                    num.z = fmaf(e2, m.z * a, num.z);
                    num.w = fmaf(e3, m.w * a, num.w);
                }
            }
        }
    }
#pragma unroll
    for (int o = 4; o < 32; o <<= 1) {
        num.x += __shfl_xor_sync(0xffffffffu, num.x, o);
        num.y += __shfl_xor_sync(0xffffffffu, num.y, o);
        num.z += __shfl_xor_sync(0xffffffffu, num.z, o);
        num.w += __shfl_xor_sync(0xffffffffu, num.w, o);
        den.x += __shfl_xor_sync(0xffffffffu, den.x, o);
        den.y += __shfl_xor_sync(0xffffffffu, den.y, o);
        den.z += __shfl_xor_sync(0xffffffffu, den.z, o);
        den.w += __shfl_xor_sync(0xffffffffu, den.w, o);
    }
    if (e8 == 0) {
        float4 b4 = *(const float4*)(bias + q * 4);
        float4 l4 = *(const float4*)(g_lin1 + node * 16 + q * 4);
        float4 o4;
        float g0 = (den.x > 0.f) ? __fdividef(num.x, den.x) : 0.f;
        float g1 = (den.y > 0.f) ? __fdividef(num.y, den.y) : 0.f;
        float g2v = (den.z > 0.f) ? __fdividef(num.z, den.z) : 0.f;
        float g3 = (den.w > 0.f) ? __fdividef(num.w, den.w) : 0.f;
        o4.x = fmaxf(g0 + b4.x + l4.x, 0.f);
        o4.y = fmaxf(g1 + b4.y + l4.y, 0.f);
        o4.z = fmaxf(g2v + b4.z + l4.z, 0.f);
        o4.w = fmaxf(g3 + b4.w + l4.w, 0.f);
        *(float4*)(g_h + node * 16 + q * 4) = o4;
    }
}

// ---------------- layer-2 node GEMM (+ overflow counter hand-off) -----------
__global__ void __launch_bounds__(256) k_gemm2(
    const float* __restrict__ Wl, const float* __restrict__ Wr,
    const float* __restrict__ Wlin, const float* __restrict__ blin)
{
    if (blockIdx.x == 0 && threadIdx.x == 0) {
        g_ovf_cnt2 = g_ovf_cnt;
        g_ovf_cnt = 0;
    }
    __shared__ float sw[16 * 24];
    int t = threadIdx.x;
    for (int idx = t; idx < 16 * 24; idx += 256) {
        int k = idx / 24, j = idx % 24;
        float v;
        if (j < 8)       v = Wl[k * 8 + j];
        else if (j < 16) v = Wr[k * 8 + j - 8];
        else             v = Wlin[k * 8 + j - 16];
        sw[idx] = v;
    }
    __syncthreads();
    int i = blockIdx.x * blockDim.x + t;
    if (i >= NN) return;
    const float4* hp = (const float4*)(g_h + i * 16);
    float4 q0 = hp[0], q1 = hp[1], q2 = hp[2], q3 = hp[3];
    float h[16] = {q0.x, q0.y, q0.z, q0.w, q1.x, q1.y, q1.z, q1.w,
                   q2.x, q2.y, q2.z, q2.w, q3.x, q3.y, q3.z, q3.w};
    float acc[24];
#pragma unroll
    for (int j = 0; j < 24; j++) acc[j] = 0.f;
#pragma unroll
    for (int k = 0; k < 16; k++) {
        float hv = h[k];
#pragma unroll
        for (int j = 0; j < 24; j++) acc[j] = fmaf(hv, sw[k * 24 + j], acc[j]);
    }
#pragma unroll
    for (int j = 0; j < 8; j++) {
        g_xl2[i * 8 + j] = acc[j];
        g_xr2[i * 8 + j] = acc[8 + j];
        g_lin2[i * 8 + j] = acc[16 + j] + blin[j];
    }
}

// ------- edge kernel layer 2 (2 lanes/edge) + fused MLP head + log_sigmoid --
// deg<=48: both passes fully register-resident (static m0..m2/p0..p2, no
// dynamic indexing, no break — avoids R7's spill failure mode).
__global__ void __launch_bounds__(256) k_edge2h(
    const float* __restrict__ att, const float* __restrict__ bias,
    const float* __restrict__ tptr,
    const float* __restrict__ W3, const float* __restrict__ b3,
    const float* __restrict__ W4, const float* __restrict__ b4,
    const float* __restrict__ W5, const float* __restrict__ b5,
    const float* __restrict__ Wout, const float* __restrict__ bout,
    float* __restrict__ out)
{
    __shared__ float sm_p[8][CAP];
    int w = threadIdx.x >> 5;
    int lane = threadIdx.x & 31;
    int node = blockIdx.x * 8 + w;
    if (node >= NN) return;
    int q = lane & 1, e16 = lane >> 1;
    int deg = g_cnt[node];
    if (lane == 0) g_cnt[node] = 0;   // reset for next launch
    int degf = deg < CAP ? deg : CAP;
    const int* sp = g_srcs + node * CAP;
    float tl2e = tptr[0] * L2E;
    float4 a4 = *(const float4*)(att + q * 4);
    float4 xr = *(const float4*)(g_xr2 + node * 8 + q * 4);
    float a06x = 0.6f * L2E * a4.x, a06y = 0.6f * L2E * a4.y;
    float a06z = 0.6f * L2E * a4.z, a06w = 0.6f * L2E * a4.w;
    float a04x = 0.4f * L2E * a4.x, a04y = 0.4f * L2E * a4.y;
    float a04z = 0.4f * L2E * a4.z, a04w = 0.4f * L2E * a4.w;
    int ngroups = (degf + 15) >> 4;   // groups of 16 edges

    float4 m0, m1, m2;
    float  p0, p1, p2;
    float S = 0.f;

    // ---- pass 1: groups 0..2 register-cached (static, masked) ----
#define E2_P1(I, MI, PI)                                                     \
    if (I < ngroups) {                                                       \
        int kk = I * 16 + e16;                                               \
        bool v = kk < degf;                                                  \
        int s = sp[v ? kk : 0];                                              \
        float4 m = make_float4(0.f, 0.f, 0.f, 0.f);                          \
        if (v) m = *(const float4*)(g_xl2 + s * 8 + q * 4);                  \
        float y0 = m.x + xr.x, y1 = m.y + xr.y, y2 = m.z + xr.z, y3 = m.w + xr.w; \
        float sc = a06x * y0;                                                \
        sc = fmaf(a04x, fabsf(y0), sc);                                      \
        sc = fmaf(a06y, y1, sc); sc = fmaf(a04y, fabsf(y1), sc);             \
        sc = fmaf(a06z, y2, sc); sc = fmaf(a04z, fabsf(y2), sc);             \
        sc = fmaf(a06w, y3, sc); sc = fmaf(a04w, fabsf(y3), sc);             \
        sc += __shfl_xor_sync(0xffffffffu, sc, 1);                           \
        float p = v ? ex2f(sc) : 0.f;                                        \
        MI = m; PI = p; S += p;                                              \
    } else { MI = make_float4(0.f, 0.f, 0.f, 0.f); PI = 0.f; }

    E2_P1(0, m0, p0)
    E2_P1(1, m1, p1)
    E2_P1(2, m2, p2)
#undef E2_P1

    // ---- pass 1: groups >=3 via smem (deg in (48,128]) ----
    for (int it = 3; it < ngroups; it++) {
        int kk = it * 16 + e16;
        bool v = kk < degf;
        int s = sp[v ? kk : 0];
        float4 m = make_float4(0.f, 0.f, 0.f, 0.f);
        if (v) m = *(const float4*)(g_xl2 + s * 8 + q * 4);
        float y0 = m.x + xr.x, y1 = m.y + xr.y, y2 = m.z + xr.z, y3 = m.w + xr.w;
        float sc = a06x * y0;
        sc = fmaf(a04x, fabsf(y0), sc);
        sc = fmaf(a06y, y1, sc); sc = fmaf(a04y, fabsf(y1), sc);
        sc = fmaf(a06z, y2, sc); sc = fmaf(a04z, fabsf(y2), sc);
        sc = fmaf(a06w, y3, sc); sc = fmaf(a04w, fabsf(y3), sc);
        sc += __shfl_xor_sync(0xffffffffu, sc, 1);
        float p = v ? ex2f(sc) : 0.f;
        if (q == 0) sm_p[w][kk] = p;
        S += p;
    }
    // ---- pass 1: overflow list (cold) ----
    if (deg > CAP) {
        int ovfn = g_ovf_cnt2;
        for (int i = 0; i < ovfn; i++) {
            if (g_ovfd[i] == node) {
                float4 m = make_float4(0.f, 0.f, 0.f, 0.f);
                if (e16 == 0) m = *(const float4*)(g_xl2 + g_ovfs[i] * 8 + q * 4);
                float y0 = m.x + xr.x, y1 = m.y + xr.y, y2 = m.z + xr.z, y3 = m.w + xr.w;
                float sc = a06x * y0;
                sc = fmaf(a04x, fabsf(y0), sc);
                sc = fmaf(a06y, y1, sc); sc = fmaf(a04y, fabsf(y1), sc);
                sc = fmaf(a06z, y2, sc); sc = fmaf(a04z, fabsf(y2), sc);
                sc = fmaf(a06w, y3, sc); sc = fmaf(a04w, fabsf(y3), sc);
                sc += __shfl_xor_sync(0xffffffffu, sc, 1);
                if (e16 == 0) S += ex2f(sc);
            }
        }
    }
#pragma unroll
    for (int o = 16; o; o >>= 1) S += __shfl_xor_sync(0xffffffffu, S, o);
    float rinv = __fdividef(2.f, S);   // S counted 2x per edge
    __syncwarp();

    // ---- pass 2: groups 0..2 pure register math (validity via vm) ----
    float4 num = make_float4(0.f, 0.f, 0.f, 0.f);
    float4 den = make_float4(0.f, 0.f, 0.f, 0.f);
#define E2_P2(I, MI, PI)                                                     \
    if (I < ngroups) {                                                       \
        float vm = (I * 16 + e16 < degf) ? 1.f : 0.f;                        \
        float a = PI * rinv;                                                 \
        float we = a * tl2e;                                                 \
        float e0 = ex2f(MI.x * we) * vm;                                     \
        float e1 = ex2f(MI.y * we) * vm;                                     \
        float e2 = ex2f(MI.z * we) * vm;                                     \
        float e3 = ex2f(MI.w * we) * vm;                                     \
        den.x += e0; den.y += e1; den.z += e2; den.w += e3;                  \
        num.x = fmaf(e0, MI.x * a, num.x);                                   \
        num.y = fmaf(e1, MI.y * a, num.y);                                   \
        num.z = fmaf(e2, MI.z * a, num.z);                                   \
        num.w = fmaf(e3, MI.w * a, num.w);                                   \
    }

    E2_P2(0, m0, p0)
    E2_P2(1, m1, p1)
    E2_P2(2, m2, p2)
#undef E2_P2

    // ---- pass 2: groups >=3 re-gather + smem p ----
    for (int it = 3; it < ngroups; it++) {
        int kk = it * 16 + e16;
        bool v = kk < degf;
        float vm = v ? 1.f : 0.f;
        int s = sp[v ? kk : 0];
        float4 m = make_float4(0.f, 0.f, 0.f, 0.f);
        if (v) m = *(const float4*)(g_xl2 + s * 8 + q * 4);
        float p = sm_p[w][kk];
        float a = p * rinv;
        float we = a * tl2e;
        float e0 = ex2f(m.x * we) * vm;
        float e1 = ex2f(m.y * we) * vm;
        float e2 = ex2f(m.z * we) * vm;
        float e3 = ex2f(m.w * we) * vm;
        den.x += e0; den.y += e1; den.z += e2; den.w += e3;
        num.x = fmaf(e0, m.x * a, num.x);
        num.y = fmaf(e1, m.y * a, num.y);
        num.z = fmaf(e2, m.z * a, num.z);
        num.w = fmaf(e3, m.w * a, num.w);
    }
    // ---- pass 2: overflow list (cold) ----
    if (deg > CAP) {
        int ovfn = g_ovf_cnt2;
        for (int i = 0; i < ovfn; i++) {
            if (g_ovfd[i] == node) {
                float4 m = make_float4(0.f, 0.f, 0.f, 0.f);
                if (e16 == 0) m = *(const float4*)(g_xl2 + g_ovfs[i] * 8 + q * 4);
                float y0 = m.x + xr.x, y1 = m.y + xr.y, y2 = m.z + xr.z, y3 = m.w + xr.w;
                float sc = a06x * y0;
                sc = fmaf(a04x, fabsf(y0), sc);
                sc = fmaf(a06y, y1, sc); sc = fmaf(a04y, fabsf(y1), sc);
                sc = fmaf(a06z, y2, sc); sc = fmaf(a04z, fabsf(y2), sc);
                sc = fmaf(a06w, y3, sc); sc = fmaf(a04w, fabsf(y3), sc);
                sc += __shfl_xor_sync(0xffffffffu, sc, 1);
                if (e16 == 0) {
                    float p = ex2f(sc);
                    float a = p * rinv;
                    float we = a * tl2e;
                    float e0 = ex2f(m.x * we);
                    float e1 = ex2f(m.y * we);
                    float e2 = ex2f(m.z * we);
                    float e3 = ex2f(m.w * we);
                    den.x += e0; den.y += e1; den.z += e2; den.w += e3;
                    num.x = fmaf(e0, m.x * a, num.x);
                    num.y = fmaf(e1, m.y * a, num.y);
                    num.z = fmaf(e2, m.z * a, num.z);
                    num.w = fmaf(e3, m.w * a, num.w);
                }
            }
        }
    }
#pragma unroll
    for (int o = 2; o < 32; o <<= 1) {
        num.x += __shfl_xor_sync(0xffffffffu, num.x, o);
        num.y += __shfl_xor_sync(0xffffffffu, num.y, o);
        num.z += __shfl_xor_sync(0xffffffffu, num.z, o);
        num.w += __shfl_xor_sync(0xffffffffu, num.w, o);
        den.x += __shfl_xor_sync(0xffffffffu, den.x, o);
        den.y += __shfl_xor_sync(0xffffffffu, den.y, o);
        den.z += __shfl_xor_sync(0xffffffffu, den.z, o);
        den.w += __shfl_xor_sync(0xffffffffu, den.w, o);
    }

    // ---- fused head: lanes pair via q ----
    float4 b4v = *(const float4*)(bias + q * 4);
    float4 l4 = *(const float4*)(g_lin2 + node * 8 + q * 4);
    float hq[4];
    {
        float g0 = (den.x > 0.f) ? __fdividef(num.x, den.x) : 0.f;
        float g1 = (den.y > 0.f) ? __fdividef(num.y, den.y) : 0.f;
        float g2v = (den.z > 0.f) ? __fdividef(num.z, den.z) : 0.f;
        float g3 = (den.w > 0.f) ? __fdividef(num.w, den.w) : 0.f;
        hq[0] = fmaxf(g0 + b4v.x + l4.x, 0.f);
        hq[1] = fmaxf(g1 + b4v.y + l4.y, 0.f);
        hq[2] = fmaxf(g2v + b4v.z + l4.z, 0.f);
        hq[3] = fmaxf(g3 + b4v.w + l4.w, 0.f);
    }
    float part[8];
#pragma unroll
    for (int c = 0; c < 8; c++) {
        float acc = 0.f;
#pragma unroll
        for (int j = 0; j < 4; j++)
            acc = fmaf(hq[j], W3[(4 * q + j) * 8 + c], acc);
        part[c] = acc;
    }
#pragma unroll
    for (int c = 0; c < 8; c++)
        part[c] += __shfl_xor_sync(0xffffffffu, part[c], 1);
    if (lane == 0) {
        float s4 = b4[0];
#pragma unroll
        for (int c = 0; c < 8; c++) {
            float z = part[c] + b3[c];
            z = z > 0.f ? z : 0.f;
            s4 = fmaf(z, W4[c], s4);
        }
        s4 = s4 > 0.f ? s4 : 0.f;
        float s5 = W5[0] * s4 + b5[0];
        s5 = s5 > 0.f ? s5 : 0.f;
        float xo = Wout[0] * s5 + bout[0];
        float ls = (xo >= 0.f) ? -log1pf(expf(-xo)) : (xo - log1pf(expf(xo)));
        out[node] = ls;
    }
}

// ---------------- launch ----------------
extern "C" void kernel_launch(void* const* d_in, const int* in_sizes, int n_in,
                              void* d_out, int out_size)
{
    const float* x    = (const float*)d_in[0];
    const int*   ei   = (const int*)d_in[1];
    const int*   src  = ei;
    const int*   dst  = ei + EE;
    const float* Wl1  = (const float*)d_in[3];
    const float* Wr1  = (const float*)d_in[4];
    const float* att1 = (const float*)d_in[5];
    const float* b1   = (const float*)d_in[6];
    const float* Wlin1= (const float*)d_in[7];
    const float* blin1= (const float*)d_in[8];
    const float* Wl2  = (const float*)d_in[9];
    const float* Wr2  = (const float*)d_in[10];
    const float* att2 = (const float*)d_in[11];
    const float* b2   = (const float*)d_in[12];
    const float* Wlin2= (const float*)d_in[13];
    const float* blin2= (const float*)d_in[14];
    const float* t    = (const float*)d_in[15];
    const float* W3   = (const float*)d_in[16];
    const float* b3   = (const float*)d_in[17];
    const float* W4   = (const float*)d_in[18];
    const float* b4   = (const float*)d_in[19];
    const float* W5   = (const float*)d_in[20];
    const float* b5   = (const float*)d_in[21];
    const float* Wout = (const float*)d_in[22];
    const float* bout = (const float*)d_in[23];
    float* out = (float*)d_out;

    // 0: fused layer-1 GEMM + MLP-8 bucket scatter
    k_build<<<GEMM1_BLKS + HIST_BLKS, 256>>>(src, dst, x, Wl1, Wr1, Wlin1, blin1);
    // 1: edge layer 1
    k_edge1<<<(NN + 7) / 8, 256>>>(att1, b1, t);
    // 2: layer-2 GEMM (pool is identity) + overflow counter hand-off
    k_gemm2<<<(NN + 255) / 256, 256>>>(Wl2, Wr2, Wlin2, blin2);
    // 3: edge layer 2 + fused MLP head
    k_edge2h<<<(NN + 7) / 8, 256>>>(att2, b2, t, W3, b3, W4, b4, W5, b5, Wout, bout, out);
}